// round 3
// baseline (speedup 1.0000x reference)
#include <cuda_runtime.h>
#include <math.h>

// ---------------------------------------------------------------------------
// Problem constants
// ---------------------------------------------------------------------------
#define BB 4
#define TT 16
#define AA 512
#define ZZ 512
#define EE 64
#define HH 8
#define HDD 64
#define NFF 6
#define NROWS (BB*TT*AA)      // 32768
#define NCUR  (BB*AA)         // 2048
#define NBT   (BB*TT)         // 64

// ---------------------------------------------------------------------------
// Scratch (static device globals; no allocations allowed)
// ---------------------------------------------------------------------------
__device__ float d_qln[NROWS*ZZ];        // LN(z_pred); reused as gate hidden
__device__ float d_q[NROWS*ZZ];          // q projection
__device__ float d_att[NROWS*ZZ];        // attention out; reused as z_mid
__device__ float d_o[NROWS*ZZ];          // out = att @ Wo
__device__ float d_hidden[NROWS*4*ZZ];   // FF hidden (32768 x 2048)
__device__ float d_kc[NCUR*ZZ];
__device__ float d_vc[NCUR*ZZ];
__device__ float d_e[NBT*ZZ];

// ---------------------------------------------------------------------------
// Helpers
// ---------------------------------------------------------------------------
__device__ __forceinline__ float gelu_exact(float x) {
    return 0.5f * x * (1.0f + erff(x * 0.70710678118654752f));
}

// block of 128 threads: sum-reduce, result broadcast to all threads
__device__ __forceinline__ float blockSum128(float v, float* sb) {
    #pragma unroll
    for (int o = 16; o > 0; o >>= 1) v += __shfl_down_sync(0xffffffffu, v, o);
    int w = threadIdx.x >> 5;
    if ((threadIdx.x & 31) == 0) sb[w] = v;
    __syncthreads();
    if (threadIdx.x < 32) {
        float r = (threadIdx.x < 4) ? sb[threadIdx.x] : 0.0f;
        #pragma unroll
        for (int o = 2; o > 0; o >>= 1) r += __shfl_down_sync(0xffffffffu, r, o);
        if (threadIdx.x == 0) sb[0] = r;
    }
    __syncthreads();
    float out = sb[0];
    __syncthreads();
    return out;
}

// ---------------------------------------------------------------------------
// LayerNorm (per 512-wide row), 128 threads/row
// ---------------------------------------------------------------------------
__global__ void ln_kernel(const float* __restrict__ x,
                          const float* __restrict__ g,
                          const float* __restrict__ b,
                          float* __restrict__ y) {
    __shared__ float sb[32];
    int row = blockIdx.x;
    int tid = threadIdx.x;
    const float* xr = x + (size_t)row * ZZ;
    float v[4];
    float s = 0.f;
    #pragma unroll
    for (int k = 0; k < 4; k++) { v[k] = xr[tid + k * 128]; s += v[k]; }
    float mean = blockSum128(s, sb) * (1.0f / ZZ);
    float s2 = 0.f;
    #pragma unroll
    for (int k = 0; k < 4; k++) { float d = v[k] - mean; s2 += d * d; }
    float var = blockSum128(s2, sb) * (1.0f / ZZ);
    float rstd = rsqrtf(var + 1e-5f);
    float* yr = y + (size_t)row * ZZ;
    #pragma unroll
    for (int k = 0; k < 4; k++) {
        int c = tid + k * 128;
        yr[c] = (v[k] - mean) * rstd * g[c] + b[c];
    }
}

// ---------------------------------------------------------------------------
// Edge embedding: fourier(actions) @ W_edge + b_edge -> @ We   (64 rows)
// ---------------------------------------------------------------------------
__global__ void edge_kernel(const float* __restrict__ actions,
                            const float* __restrict__ W_edge,
                            const float* __restrict__ b_edge,
                            const float* __restrict__ We,
                            float* __restrict__ eout) {
    __shared__ float feats[38];
    __shared__ float hid[64];
    int bt = blockIdx.x;
    int tid = threadIdx.x;
    if (tid == 0) {
        float dx = actions[bt * 4 + 0];
        float dy = actions[bt * 4 + 1];
        float th = actions[bt * 4 + 2];
        feats[0] = sinf(th);
        feats[1] = cosf(th);
        #pragma unroll
        for (int k = 0; k < NFF; k++) {
            float f = 3.14159265358979323846f * (float)(1 << k);
            feats[2 + 6 * k + 0] = sinf(f * dx);
            feats[2 + 6 * k + 1] = cosf(f * dx);
            feats[2 + 6 * k + 2] = sinf(f * dy);
            feats[2 + 6 * k + 3] = cosf(f * dy);
            feats[2 + 6 * k + 4] = sinf(f * th);
            feats[2 + 6 * k + 5] = cosf(f * th);
        }
    }
    __syncthreads();
    float h = b_edge[tid];
    #pragma unroll
    for (int j = 0; j < 38; j++) h += feats[j] * W_edge[j * 64 + tid];
    hid[tid] = h;
    __syncthreads();
    #pragma unroll
    for (int c = 0; c < 8; c++) {
        int col = c * 64 + tid;
        float acc = 0.f;
        #pragma unroll
        for (int j = 0; j < 64; j++) acc += hid[j] * We[j * ZZ + col];
        eout[(size_t)bt * ZZ + col] = acc;
    }
}

// ---------------------------------------------------------------------------
// Tiled SGEMM: C[N,M] (=|+=) A[N,K] @ B[K,M]  (+bias)(gelu)(+res)
// BM=BN=128, BK=16, 256 threads, 8x8 per thread. All dims multiples.
// ---------------------------------------------------------------------------
template<bool ACC, bool BIAS, bool GELU, bool RES>
__global__ void __launch_bounds__(256, 2)
sgemm(const float* __restrict__ Ag, const float* __restrict__ Bg,
      const float* __restrict__ bias, const float* __restrict__ res,
      float* __restrict__ C, int N, int K, int M) {
    __shared__ float As[16][128];
    __shared__ float Bs[16][128];
    const int bRow = blockIdx.y * 128;
    const int bCol = blockIdx.x * 128;
    const int tid = threadIdx.x;
    const int tRow = (tid / 16) * 8;
    const int tCol = (tid % 16) * 8;

    float acc[8][8];
    #pragma unroll
    for (int i = 0; i < 8; i++)
        #pragma unroll
        for (int j = 0; j < 8; j++) acc[i][j] = 0.f;

    for (int k0 = 0; k0 < K; k0 += 16) {
        #pragma unroll
        for (int it = 0; it < 2; it++) {
            int idx = tid + it * 256;
            int r = idx >> 2, cg = idx & 3;
            float4 v = *(const float4*)(Ag + (size_t)(bRow + r) * K + k0 + cg * 4);
            As[cg * 4 + 0][r] = v.x;
            As[cg * 4 + 1][r] = v.y;
            As[cg * 4 + 2][r] = v.z;
            As[cg * 4 + 3][r] = v.w;
        }
        #pragma unroll
        for (int it = 0; it < 2; it++) {
            int idx = tid + it * 256;
            int r = idx >> 5, cg = idx & 31;
            *(float4*)(&Bs[r][cg * 4]) =
                *(const float4*)(Bg + (size_t)(k0 + r) * M + bCol + cg * 4);
        }
        __syncthreads();
        #pragma unroll
        for (int kk = 0; kk < 16; kk++) {
            float ra[8], rb[8];
            *(float4*)(&ra[0]) = *(const float4*)(&As[kk][tRow]);
            *(float4*)(&ra[4]) = *(const float4*)(&As[kk][tRow + 4]);
            *(float4*)(&rb[0]) = *(const float4*)(&Bs[kk][tCol]);
            *(float4*)(&rb[4]) = *(const float4*)(&Bs[kk][tCol + 4]);
            #pragma unroll
            for (int i = 0; i < 8; i++)
                #pragma unroll
                for (int j = 0; j < 8; j++)
                    acc[i][j] = fmaf(ra[i], rb[j], acc[i][j]);
        }
        __syncthreads();
    }

    #pragma unroll
    for (int i = 0; i < 8; i++) {
        int row = bRow + tRow + i;
        #pragma unroll
        for (int j = 0; j < 8; j++) {
            int col = bCol + tCol + j;
            size_t idx = (size_t)row * M + col;
            float c = acc[i][j];
            if (ACC)  c += C[idx];
            if (BIAS) c += bias[col];
            if (GELU) c = gelu_exact(c);
            if (RES)  c += res[idx];
            C[idx] = c;
        }
    }
}

// ---------------------------------------------------------------------------
// Per-dim head-mixing attention.
// logits[b,t,a,d,i,j] = q[bta, i*64+d] * (kc[ba, j*64+d]+e[bt, j*64+d]) / 8
// softmax over j (8), out[bta, i*64+d] = sum_j p * vc[ba, j*64+d]
// one thread per (row, d): 32768*64 threads.
// ---------------------------------------------------------------------------
__global__ void attn_kernel(const float* __restrict__ q,
                            const float* __restrict__ kc,
                            const float* __restrict__ vc,
                            const float* __restrict__ e,
                            float* __restrict__ att) {
    int idx = blockIdx.x * blockDim.x + threadIdx.x;
    int d = idx & 63;
    int row = idx >> 6;          // bta
    int a = row & (AA - 1);
    int bt = row >> 9;
    int b = bt >> 4;
    const float* qr = q + (size_t)row * ZZ;
    const float* kr = kc + (size_t)(b * AA + a) * ZZ;
    const float* vr = vc + (size_t)(b * AA + a) * ZZ;
    const float* er = e + (size_t)bt * ZZ;
    float qv[8], kv[8], vv[8];
    #pragma unroll
    for (int h = 0; h < 8; h++) {
        int o = h * 64 + d;
        qv[h] = qr[o] * 0.125f;
        kv[h] = kr[o] + er[o];
        vv[h] = vr[o];
    }
    float* outr = att + (size_t)row * ZZ;
    #pragma unroll
    for (int i = 0; i < 8; i++) {
        float l[8], m = -1e30f;
        #pragma unroll
        for (int j = 0; j < 8; j++) { l[j] = qv[i] * kv[j]; m = fmaxf(m, l[j]); }
        float s = 0.f, o = 0.f;
        #pragma unroll
        for (int j = 0; j < 8; j++) {
            float p = expf(l[j] - m);
            s += p;
            o += p * vv[j];
        }
        outr[i * 64 + d] = o / s;
    }
}

// ---------------------------------------------------------------------------
// Gate scalar + z_mid LN, 128 threads/row
// g = sigmoid(h . Wg2 + bg2); y = z_pred + g*out; z_mid = LN(y)*g_lno+b_lno
// ---------------------------------------------------------------------------
__global__ void gate_zmid_kernel(const float* __restrict__ hgate,
                                 const float* __restrict__ Wg2,
                                 const float* __restrict__ bg2,
                                 const float* __restrict__ zpred,
                                 const float* __restrict__ outb,
                                 const float* __restrict__ g_lno,
                                 const float* __restrict__ b_lno,
                                 float* __restrict__ zmid) {
    __shared__ float sb[32];
    int row = blockIdx.x;
    int tid = threadIdx.x;
    const float* hr = hgate + (size_t)row * ZZ;
    float p = 0.f;
    #pragma unroll
    for (int k = 0; k < 4; k++) {
        int c = tid + k * 128;
        p += hr[c] * Wg2[c];
    }
    float dot = blockSum128(p, sb);
    float g = 1.0f / (1.0f + expf(-(dot + bg2[0])));

    const float* zr = zpred + (size_t)row * ZZ;
    const float* orow = outb + (size_t)row * ZZ;
    float y[4];
    float s = 0.f;
    #pragma unroll
    for (int k = 0; k < 4; k++) {
        int c = tid + k * 128;
        y[k] = zr[c] + g * orow[c];
        s += y[k];
    }
    float mean = blockSum128(s, sb) * (1.0f / ZZ);
    float s2 = 0.f;
    #pragma unroll
    for (int k = 0; k < 4; k++) { float d = y[k] - mean; s2 += d * d; }
    float var = blockSum128(s2, sb) * (1.0f / ZZ);
    float rstd = rsqrtf(var + 1e-5f);
    float* zm = zmid + (size_t)row * ZZ;
    #pragma unroll
    for (int k = 0; k < 4; k++) {
        int c = tid + k * 128;
        zm[c] = (y[k] - mean) * rstd * g_lno[c] + b_lno[c];
    }
}

// ---------------------------------------------------------------------------
// Launch
// ---------------------------------------------------------------------------
extern "C" void kernel_launch(void* const* d_in, const int* in_sizes, int n_in,
                              void* d_out, int out_size) {
    const float* z_current = (const float*)d_in[0];
    const float* z_pred    = (const float*)d_in[1];
    const float* actions   = (const float*)d_in[2];
    const float* Wq        = (const float*)d_in[3];
    const float* Wk        = (const float*)d_in[4];
    const float* Wv        = (const float*)d_in[5];
    const float* We        = (const float*)d_in[6];
    const float* Wo        = (const float*)d_in[7];
    const float* g_lnq     = (const float*)d_in[8];
    const float* b_lnq     = (const float*)d_in[9];
    const float* g_lno     = (const float*)d_in[10];
    const float* b_lno     = (const float*)d_in[11];
    const float* W_ff1     = (const float*)d_in[12];
    const float* b_ff1     = (const float*)d_in[13];
    const float* W_ff2     = (const float*)d_in[14];
    const float* b_ff2     = (const float*)d_in[15];
    const float* W_edge    = (const float*)d_in[16];
    const float* b_edge    = (const float*)d_in[17];
    const float* Wg1       = (const float*)d_in[18];
    const float* bg1       = (const float*)d_in[19];
    const float* Wg2       = (const float*)d_in[20];
    const float* bg2       = (const float*)d_in[21];
    float* out = (float*)d_out;

    void *p_qln, *p_q, *p_att, *p_o, *p_hid, *p_kc, *p_vc, *p_e;
    cudaGetSymbolAddress(&p_qln, d_qln);
    cudaGetSymbolAddress(&p_q,   d_q);
    cudaGetSymbolAddress(&p_att, d_att);
    cudaGetSymbolAddress(&p_o,   d_o);
    cudaGetSymbolAddress(&p_hid, d_hidden);
    cudaGetSymbolAddress(&p_kc,  d_kc);
    cudaGetSymbolAddress(&p_vc,  d_vc);
    cudaGetSymbolAddress(&p_e,   d_e);
    float* qln = (float*)p_qln;   // later: gate hidden
    float* q   = (float*)p_q;
    float* att = (float*)p_att;   // later: z_mid
    float* o   = (float*)p_o;
    float* hid = (float*)p_hid;
    float* kc  = (float*)p_kc;
    float* vc  = (float*)p_vc;
    float* e   = (float*)p_e;

    // 1) LN(z_pred) -> qln
    ln_kernel<<<NROWS, 128>>>(z_pred, g_lnq, b_lnq, qln);
    // 2) edge embedding
    edge_kernel<<<NBT, 64>>>(actions, W_edge, b_edge, We, e);
    // 3) q = qln @ Wq
    sgemm<false,false,false,false><<<dim3(ZZ/128, NROWS/128), 256>>>(
        qln, Wq, nullptr, nullptr, q, NROWS, ZZ, ZZ);
    // 4) kc, vc
    sgemm<false,false,false,false><<<dim3(ZZ/128, NCUR/128), 256>>>(
        z_current, Wk, nullptr, nullptr, kc, NCUR, ZZ, ZZ);
    sgemm<false,false,false,false><<<dim3(ZZ/128, NCUR/128), 256>>>(
        z_current, Wv, nullptr, nullptr, vc, NCUR, ZZ, ZZ);
    // 5) attention
    attn_kernel<<<(NROWS * 64) / 256, 256>>>(q, kc, vc, e, att);
    // 6) o = att @ Wo
    sgemm<false,false,false,false><<<dim3(ZZ/128, NROWS/128), 256>>>(
        att, Wo, nullptr, nullptr, o, NROWS, ZZ, ZZ);
    // 7) gate hidden = gelu(o @ Wg1_top + z_pred @ Wg1_bot + bg1) -> qln
    sgemm<false,false,false,false><<<dim3(ZZ/128, NROWS/128), 256>>>(
        o, Wg1, nullptr, nullptr, qln, NROWS, ZZ, ZZ);
    sgemm<true,true,true,false><<<dim3(ZZ/128, NROWS/128), 256>>>(
        z_pred, Wg1 + (size_t)ZZ * ZZ, bg1, nullptr, qln, NROWS, ZZ, ZZ);
    // 8) gate scalar + z_mid -> att buffer
    gate_zmid_kernel<<<NROWS, 128>>>(qln, Wg2, bg2, z_pred, o, g_lno, b_lno, att);
    // 9) hidden = gelu(z_mid @ W_ff1 + b_ff1)
    sgemm<false,true,true,false><<<dim3((4*ZZ)/128, NROWS/128), 256>>>(
        att, W_ff1, b_ff1, nullptr, hid, NROWS, ZZ, 4*ZZ);
    // 10) out = hidden @ W_ff2 + b_ff2 + z_mid
    sgemm<false,true,false,true><<<dim3(ZZ/128, NROWS/128), 256>>>(
        hid, W_ff2, b_ff2, att, out, NROWS, 4*ZZ, ZZ);
}

// round 4
// speedup vs baseline: 3.0717x; 3.0717x over previous
#include <cuda_runtime.h>
#include <math.h>
#include <stdint.h>

// ---------------------------------------------------------------------------
// Problem constants
// ---------------------------------------------------------------------------
#define BB 4
#define TT 16
#define AA 512
#define ZZ 512
#define NFF 6
#define NROWS (BB*TT*AA)      // 32768
#define NCUR  (BB*AA)         // 2048
#define NBT   (BB*TT)         // 64

// ---------------------------------------------------------------------------
// Scratch (static device globals; no allocations allowed)
// ---------------------------------------------------------------------------
__device__ float d_qln[NROWS*ZZ];        // LN(z_pred) tf32; reused as gate hidden
__device__ float d_q[NROWS*ZZ];          // q projection; reused as z_mid (tf32)
__device__ float d_att[NROWS*ZZ];        // attention out (tf32); reused as z_mid fp32
__device__ float d_o[NROWS*ZZ];          // out = att @ Wo (tf32)
__device__ float d_hidden[NROWS*4*ZZ];   // FF hidden (tf32)
__device__ float d_kc[NCUR*ZZ];
__device__ float d_vc[NCUR*ZZ];
__device__ float d_e[NBT*ZZ];
__device__ float d_zcr[NCUR*ZZ];         // tf32-rounded z_current
__device__ float d_zpr[NROWS*ZZ];        // tf32-rounded z_pred
__device__ float d_wr[3670016];          // tf32-rounded weights (packed)

// offsets into d_wr
#define OFF_WQ   0
#define OFF_WK   262144
#define OFF_WV   524288
#define OFF_WO   786432
#define OFF_WG1  1048576
#define OFF_FF1  1572864
#define OFF_FF2  2621440

// ---------------------------------------------------------------------------
// Helpers
// ---------------------------------------------------------------------------
__device__ __forceinline__ float gelu_exact(float x) {
    return 0.5f * x * (1.0f + erff(x * 0.70710678118654752f));
}
__device__ __forceinline__ float tf32r(float x) {
    uint32_t u;
    asm("cvt.rna.tf32.f32 %0, %1;" : "=r"(u) : "f"(x));
    return __uint_as_float(u);
}
__device__ __forceinline__ void cp_async16(uint32_t s, const void* g) {
    asm volatile("cp.async.cg.shared.global [%0], [%1], 16;" :: "r"(s), "l"(g));
}
__device__ __forceinline__ void cp_commit() {
    asm volatile("cp.async.commit_group;");
}
__device__ __forceinline__ void cp_wait1() {
    asm volatile("cp.async.wait_group 1;");
}
__device__ __forceinline__ void cp_wait0() {
    asm volatile("cp.async.wait_group 0;");
}

__device__ __forceinline__ float blockSum128(float v, float* sb) {
    #pragma unroll
    for (int o = 16; o > 0; o >>= 1) v += __shfl_down_sync(0xffffffffu, v, o);
    int w = threadIdx.x >> 5;
    if ((threadIdx.x & 31) == 0) sb[w] = v;
    __syncthreads();
    if (threadIdx.x < 32) {
        float r = (threadIdx.x < 4) ? sb[threadIdx.x] : 0.0f;
        #pragma unroll
        for (int o = 2; o > 0; o >>= 1) r += __shfl_down_sync(0xffffffffu, r, o);
        if (threadIdx.x == 0) sb[0] = r;
    }
    __syncthreads();
    float out = sb[0];
    __syncthreads();
    return out;
}

// ---------------------------------------------------------------------------
// Elementwise tf32 round-copy (n divisible by 4)
// ---------------------------------------------------------------------------
__global__ void roundcopy(const float* __restrict__ x, float* __restrict__ y, int n4) {
    int i = blockIdx.x * blockDim.x + threadIdx.x;
    if (i < n4) {
        float4 v = ((const float4*)x)[i];
        v.x = tf32r(v.x); v.y = tf32r(v.y); v.z = tf32r(v.z); v.w = tf32r(v.w);
        ((float4*)y)[i] = v;
    }
}

// ---------------------------------------------------------------------------
// LayerNorm (per 512-wide row), 128 threads/row; output tf32-rounded
// ---------------------------------------------------------------------------
__global__ void ln_kernel(const float* __restrict__ x,
                          const float* __restrict__ g,
                          const float* __restrict__ b,
                          float* __restrict__ y) {
    __shared__ float sb[32];
    int row = blockIdx.x;
    int tid = threadIdx.x;
    const float* xr = x + (size_t)row * ZZ;
    float v[4];
    float s = 0.f;
    #pragma unroll
    for (int k = 0; k < 4; k++) { v[k] = xr[tid + k * 128]; s += v[k]; }
    float mean = blockSum128(s, sb) * (1.0f / ZZ);
    float s2 = 0.f;
    #pragma unroll
    for (int k = 0; k < 4; k++) { float d = v[k] - mean; s2 += d * d; }
    float var = blockSum128(s2, sb) * (1.0f / ZZ);
    float rstd = rsqrtf(var + 1e-5f);
    float* yr = y + (size_t)row * ZZ;
    #pragma unroll
    for (int k = 0; k < 4; k++) {
        int c = tid + k * 128;
        yr[c] = tf32r((v[k] - mean) * rstd * g[c] + b[c]);
    }
}

// ---------------------------------------------------------------------------
// Edge embedding: fourier(actions) @ W_edge + b_edge -> @ We   (64 rows)
// ---------------------------------------------------------------------------
__global__ void edge_kernel(const float* __restrict__ actions,
                            const float* __restrict__ W_edge,
                            const float* __restrict__ b_edge,
                            const float* __restrict__ We,
                            float* __restrict__ eout) {
    __shared__ float feats[38];
    __shared__ float hid[64];
    int bt = blockIdx.x;
    int tid = threadIdx.x;
    if (tid == 0) {
        float dx = actions[bt * 4 + 0];
        float dy = actions[bt * 4 + 1];
        float th = actions[bt * 4 + 2];
        feats[0] = sinf(th);
        feats[1] = cosf(th);
        #pragma unroll
        for (int k = 0; k < NFF; k++) {
            float f = 3.14159265358979323846f * (float)(1 << k);
            feats[2 + 6 * k + 0] = sinf(f * dx);
            feats[2 + 6 * k + 1] = cosf(f * dx);
            feats[2 + 6 * k + 2] = sinf(f * dy);
            feats[2 + 6 * k + 3] = cosf(f * dy);
            feats[2 + 6 * k + 4] = sinf(f * th);
            feats[2 + 6 * k + 5] = cosf(f * th);
        }
    }
    __syncthreads();
    float h = b_edge[tid];
    #pragma unroll
    for (int j = 0; j < 38; j++) h += feats[j] * W_edge[j * 64 + tid];
    hid[tid] = h;
    __syncthreads();
    #pragma unroll
    for (int c = 0; c < 8; c++) {
        int col = c * 64 + tid;
        float acc = 0.f;
        #pragma unroll
        for (int j = 0; j < 64; j++) acc += hid[j] * We[j * ZZ + col];
        eout[(size_t)bt * ZZ + col] = acc;
    }
}

// ---------------------------------------------------------------------------
// TF32 tensor-core GEMM: C[N,M] = A[N,K] @ B[K,M] (+C)(+bias)(gelu)(+res)(round)
// 128x128x32 tiles, cp.async double buffer, 8 warps of 64x32, mma m16n8k8.
// A and B MUST be tf32-rounded already. All dims multiples of 128 (K of 32).
// ---------------------------------------------------------------------------
#define MM_SMEM ((2*128*36 + 2*32*132) * 4)

__device__ __forceinline__ void mma8(float c[4], uint32_t a0, uint32_t a1,
                                     uint32_t a2, uint32_t a3,
                                     uint32_t b0, uint32_t b1) {
    asm volatile(
        "mma.sync.aligned.m16n8k8.row.col.f32.tf32.tf32.f32 "
        "{%0,%1,%2,%3},{%4,%5,%6,%7},{%8,%9},{%0,%1,%2,%3};"
        : "+f"(c[0]), "+f"(c[1]), "+f"(c[2]), "+f"(c[3])
        : "r"(a0), "r"(a1), "r"(a2), "r"(a3), "r"(b0), "r"(b1));
}

template<bool ACC, bool BIAS, bool GELU, bool RES, bool ROUND>
__global__ void __launch_bounds__(256, 2)
mm_tf32(const float* __restrict__ A, const float* __restrict__ Bw,
        const float* __restrict__ bias, const float* __restrict__ res,
        float* __restrict__ C, int N, int K, int M) {
    extern __shared__ float sm[];
    float* As = sm;               // [2][128][36]
    float* Bs = sm + 2 * 128 * 36;  // [2][32][132]

    const int tid = threadIdx.x;
    const int lane = tid & 31;
    const int wid = tid >> 5;
    const int wm = (wid >> 2) * 64;
    const int wn = (wid & 3) * 32;
    const int bRow = blockIdx.y * 128;
    const int bCol = blockIdx.x * 128;
    const int gid = lane >> 2;    // groupID
    const int tig = lane & 3;     // thread in group

    float acc[4][4][4];
    #pragma unroll
    for (int mi = 0; mi < 4; mi++)
        #pragma unroll
        for (int ni = 0; ni < 4; ni++)
            #pragma unroll
            for (int r = 0; r < 4; r++) acc[mi][ni][r] = 0.f;

    const int ar = tid >> 3, ac = (tid & 7) * 4;       // A: 128 rows x 8 f4
    const int br = tid >> 5, bc = (tid & 31) * 4;      // B: 32 rows x 32 f4

    // tile loaders: 4 chunks each (idx stepping by 256 rows-equivalent)
    #define LOAD_A(buf, k0)                                                     \
        { _Pragma("unroll")                                                     \
          for (int it = 0; it < 4; it++) {                                      \
              int r = ar + it * 32;                                             \
              uint32_t s = (uint32_t)__cvta_generic_to_shared(                  \
                  &As[(buf) * 128 * 36 + r * 36 + ac]);                         \
              cp_async16(s, A + (size_t)(bRow + r) * K + (k0) + ac);            \
          } }
    #define LOAD_B(buf, k0)                                                     \
        { _Pragma("unroll")                                                     \
          for (int it = 0; it < 4; it++) {                                      \
              int r = br + it * 8;                                              \
              uint32_t s = (uint32_t)__cvta_generic_to_shared(                  \
                  &Bs[(buf) * 32 * 132 + r * 132 + bc]);                        \
              cp_async16(s, Bw + (size_t)((k0) + r) * M + bCol + bc);           \
          } }

    LOAD_A(0, 0); LOAD_B(0, 0); cp_commit();

    const int nk = K >> 5;
    int buf = 0;
    for (int kt = 0; kt < nk; kt++) {
        if (kt + 1 < nk) {
            LOAD_A(buf ^ 1, (kt + 1) * 32);
            LOAD_B(buf ^ 1, (kt + 1) * 32);
            cp_commit();
            cp_wait1();
        } else {
            cp_wait0();
        }
        __syncthreads();

        const float* as = &As[buf * 128 * 36];
        const float* bs = &Bs[buf * 32 * 132];
        #pragma unroll
        for (int ks = 0; ks < 4; ks++) {
            uint32_t bfr[4][2];
            #pragma unroll
            for (int ni = 0; ni < 4; ni++) {
                int cc = wn + ni * 8 + gid;
                int kk = ks * 8 + tig;
                bfr[ni][0] = __float_as_uint(bs[kk * 132 + cc]);
                bfr[ni][1] = __float_as_uint(bs[(kk + 4) * 132 + cc]);
            }
            #pragma unroll
            for (int mi = 0; mi < 4; mi++) {
                int r = wm + mi * 16 + gid;
                int c = ks * 8 + tig;
                uint32_t a0 = __float_as_uint(as[r * 36 + c]);
                uint32_t a1 = __float_as_uint(as[(r + 8) * 36 + c]);
                uint32_t a2 = __float_as_uint(as[r * 36 + c + 4]);
                uint32_t a3 = __float_as_uint(as[(r + 8) * 36 + c + 4]);
                #pragma unroll
                for (int ni = 0; ni < 4; ni++)
                    mma8(acc[mi][ni], a0, a1, a2, a3, bfr[ni][0], bfr[ni][1]);
            }
        }
        __syncthreads();
        buf ^= 1;
    }

    // epilogue
    #pragma unroll
    for (int mi = 0; mi < 4; mi++) {
        #pragma unroll
        for (int ni = 0; ni < 4; ni++) {
            int r0 = bRow + wm + mi * 16 + gid;
            int c0 = bCol + wn + ni * 8 + tig * 2;
            #pragma unroll
            for (int half = 0; half < 2; half++) {
                int r = r0 + half * 8;
                size_t idx = (size_t)r * M + c0;
                float e0 = acc[mi][ni][half * 2 + 0];
                float e1 = acc[mi][ni][half * 2 + 1];
                if (ACC)  { e0 += C[idx]; e1 += C[idx + 1]; }
                if (BIAS) { e0 += bias[c0]; e1 += bias[c0 + 1]; }
                if (GELU) { e0 = gelu_exact(e0); e1 = gelu_exact(e1); }
                if (RES)  { e0 += res[idx]; e1 += res[idx + 1]; }
                if (ROUND){ e0 = tf32r(e0); e1 = tf32r(e1); }
                float2 v = make_float2(e0, e1);
                *(float2*)(C + idx) = v;
            }
        }
    }
    #undef LOAD_A
    #undef LOAD_B
}

// ---------------------------------------------------------------------------
// Per-dim head-mixing attention (output tf32-rounded; feeds Wo GEMM)
// ---------------------------------------------------------------------------
__global__ void attn_kernel(const float* __restrict__ q,
                            const float* __restrict__ kc,
                            const float* __restrict__ vc,
                            const float* __restrict__ e,
                            float* __restrict__ att) {
    int idx = blockIdx.x * blockDim.x + threadIdx.x;
    int d = idx & 63;
    int row = idx >> 6;          // bta
    int a = row & (AA - 1);
    int bt = row >> 9;
    int b = bt >> 4;
    const float* qr = q + (size_t)row * ZZ;
    const float* kr = kc + (size_t)(b * AA + a) * ZZ;
    const float* vr = vc + (size_t)(b * AA + a) * ZZ;
    const float* er = e + (size_t)bt * ZZ;
    float qv[8], kv[8], vv[8];
    #pragma unroll
    for (int h = 0; h < 8; h++) {
        int o = h * 64 + d;
        qv[h] = qr[o] * 0.125f;
        kv[h] = kr[o] + er[o];
        vv[h] = vr[o];
    }
    float* outr = att + (size_t)row * ZZ;
    #pragma unroll
    for (int i = 0; i < 8; i++) {
        float l[8], m = -1e30f;
        #pragma unroll
        for (int j = 0; j < 8; j++) { l[j] = qv[i] * kv[j]; m = fmaxf(m, l[j]); }
        float s = 0.f, o = 0.f;
        #pragma unroll
        for (int j = 0; j < 8; j++) {
            float p = expf(l[j] - m);
            s += p;
            o += p * vv[j];
        }
        outr[i * 64 + d] = tf32r(o / s);
    }
}

// ---------------------------------------------------------------------------
// Gate scalar + z_mid LN, 128 threads/row
// writes zmid (fp32, for FF2 residual) and zmidR (tf32, FF1 input)
// ---------------------------------------------------------------------------
__global__ void gate_zmid_kernel(const float* __restrict__ hgate,
                                 const float* __restrict__ Wg2,
                                 const float* __restrict__ bg2,
                                 const float* __restrict__ zpred,
                                 const float* __restrict__ outb,
                                 const float* __restrict__ g_lno,
                                 const float* __restrict__ b_lno,
                                 float* __restrict__ zmid,
                                 float* __restrict__ zmidR) {
    __shared__ float sb[32];
    int row = blockIdx.x;
    int tid = threadIdx.x;
    const float* hr = hgate + (size_t)row * ZZ;
    float p = 0.f;
    #pragma unroll
    for (int k = 0; k < 4; k++) {
        int c = tid + k * 128;
        p += hr[c] * Wg2[c];
    }
    float dot = blockSum128(p, sb);
    float g = 1.0f / (1.0f + expf(-(dot + bg2[0])));

    const float* zr = zpred + (size_t)row * ZZ;
    const float* orow = outb + (size_t)row * ZZ;
    float y[4];
    float s = 0.f;
    #pragma unroll
    for (int k = 0; k < 4; k++) {
        int c = tid + k * 128;
        y[k] = zr[c] + g * orow[c];
        s += y[k];
    }
    float mean = blockSum128(s, sb) * (1.0f / ZZ);
    float s2 = 0.f;
    #pragma unroll
    for (int k = 0; k < 4; k++) { float d = y[k] - mean; s2 += d * d; }
    float var = blockSum128(s2, sb) * (1.0f / ZZ);
    float rstd = rsqrtf(var + 1e-5f);
    float* zm = zmid + (size_t)row * ZZ;
    float* zmr = zmidR + (size_t)row * ZZ;
    #pragma unroll
    for (int k = 0; k < 4; k++) {
        int c = tid + k * 128;
        float v = (y[k] - mean) * rstd * g_lno[c] + b_lno[c];
        zm[c] = v;
        zmr[c] = tf32r(v);
    }
}

// ---------------------------------------------------------------------------
// Launch
// ---------------------------------------------------------------------------
extern "C" void kernel_launch(void* const* d_in, const int* in_sizes, int n_in,
                              void* d_out, int out_size) {
    const float* z_current = (const float*)d_in[0];
    const float* z_pred    = (const float*)d_in[1];
    const float* actions   = (const float*)d_in[2];
    const float* Wq        = (const float*)d_in[3];
    const float* Wk        = (const float*)d_in[4];
    const float* Wv        = (const float*)d_in[5];
    const float* We        = (const float*)d_in[6];
    const float* Wo        = (const float*)d_in[7];
    const float* g_lnq     = (const float*)d_in[8];
    const float* b_lnq     = (const float*)d_in[9];
    const float* g_lno     = (const float*)d_in[10];
    const float* b_lno     = (const float*)d_in[11];
    const float* W_ff1     = (const float*)d_in[12];
    const float* b_ff1     = (const float*)d_in[13];
    const float* W_ff2     = (const float*)d_in[14];
    const float* b_ff2     = (const float*)d_in[15];
    const float* W_edge    = (const float*)d_in[16];
    const float* b_edge    = (const float*)d_in[17];
    const float* Wg1       = (const float*)d_in[18];
    const float* bg1       = (const float*)d_in[19];
    const float* Wg2       = (const float*)d_in[20];
    const float* bg2       = (const float*)d_in[21];
    float* out = (float*)d_out;

    void *p_qln, *p_q, *p_att, *p_o, *p_hid, *p_kc, *p_vc, *p_e, *p_zcr, *p_zpr, *p_wr;
    cudaGetSymbolAddress(&p_qln, d_qln);
    cudaGetSymbolAddress(&p_q,   d_q);
    cudaGetSymbolAddress(&p_att, d_att);
    cudaGetSymbolAddress(&p_o,   d_o);
    cudaGetSymbolAddress(&p_hid, d_hidden);
    cudaGetSymbolAddress(&p_kc,  d_kc);
    cudaGetSymbolAddress(&p_vc,  d_vc);
    cudaGetSymbolAddress(&p_e,   d_e);
    cudaGetSymbolAddress(&p_zcr, d_zcr);
    cudaGetSymbolAddress(&p_zpr, d_zpr);
    cudaGetSymbolAddress(&p_wr,  d_wr);
    float* qln = (float*)p_qln;   // later: gate hidden
    float* q   = (float*)p_q;     // later: z_mid rounded
    float* att = (float*)p_att;   // later: z_mid fp32
    float* o   = (float*)p_o;
    float* hid = (float*)p_hid;
    float* kc  = (float*)p_kc;
    float* vc  = (float*)p_vc;
    float* e   = (float*)p_e;
    float* zcr = (float*)p_zcr;
    float* zpr = (float*)p_zpr;
    float* wr  = (float*)p_wr;

    // allow 70KB dynamic smem on all GEMM instantiations (idempotent)
    cudaFuncSetAttribute(mm_tf32<false,false,false,false,false>,
                         cudaFuncAttributeMaxDynamicSharedMemorySize, MM_SMEM);
    cudaFuncSetAttribute(mm_tf32<false,false,false,false,true>,
                         cudaFuncAttributeMaxDynamicSharedMemorySize, MM_SMEM);
    cudaFuncSetAttribute(mm_tf32<true,true,true,false,false>,
                         cudaFuncAttributeMaxDynamicSharedMemorySize, MM_SMEM);
    cudaFuncSetAttribute(mm_tf32<false,true,true,false,true>,
                         cudaFuncAttributeMaxDynamicSharedMemorySize, MM_SMEM);
    cudaFuncSetAttribute(mm_tf32<false,true,false,true,false>,
                         cudaFuncAttributeMaxDynamicSharedMemorySize, MM_SMEM);

    // 0) tf32-round weights + raw GEMM inputs
    roundcopy<<<(262144/4+255)/256, 256>>>(Wq,    wr + OFF_WQ,  262144/4);
    roundcopy<<<(262144/4+255)/256, 256>>>(Wk,    wr + OFF_WK,  262144/4);
    roundcopy<<<(262144/4+255)/256, 256>>>(Wv,    wr + OFF_WV,  262144/4);
    roundcopy<<<(262144/4+255)/256, 256>>>(Wo,    wr + OFF_WO,  262144/4);
    roundcopy<<<(524288/4+255)/256, 256>>>(Wg1,   wr + OFF_WG1, 524288/4);
    roundcopy<<<(1048576/4+255)/256,256>>>(W_ff1, wr + OFF_FF1, 1048576/4);
    roundcopy<<<(1048576/4+255)/256,256>>>(W_ff2, wr + OFF_FF2, 1048576/4);
    roundcopy<<<((NCUR*ZZ)/4+255)/256, 256>>>(z_current, zcr, (NCUR*ZZ)/4);
    roundcopy<<<((NROWS*ZZ)/4+255)/256,256>>>(z_pred,    zpr, (NROWS*ZZ)/4);

    // 1) LN(z_pred) -> qln (tf32)
    ln_kernel<<<NROWS, 128>>>(z_pred, g_lnq, b_lnq, qln);
    // 2) edge embedding
    edge_kernel<<<NBT, 64>>>(actions, W_edge, b_edge, We, e);
    // 3) q = qln @ Wq
    mm_tf32<false,false,false,false,false><<<dim3(ZZ/128, NROWS/128), 256, MM_SMEM>>>(
        qln, wr + OFF_WQ, nullptr, nullptr, q, NROWS, ZZ, ZZ);
    // 4) kc, vc
    mm_tf32<false,false,false,false,false><<<dim3(ZZ/128, NCUR/128), 256, MM_SMEM>>>(
        zcr, wr + OFF_WK, nullptr, nullptr, kc, NCUR, ZZ, ZZ);
    mm_tf32<false,false,false,false,false><<<dim3(ZZ/128, NCUR/128), 256, MM_SMEM>>>(
        zcr, wr + OFF_WV, nullptr, nullptr, vc, NCUR, ZZ, ZZ);
    // 5) attention -> att (tf32)
    attn_kernel<<<(NROWS * 64) / 256, 256>>>(q, kc, vc, e, att);
    // 6) o = att @ Wo  (tf32-rounded out, feeds gate GEMM + residual)
    mm_tf32<false,false,false,false,true><<<dim3(ZZ/128, NROWS/128), 256, MM_SMEM>>>(
        att, wr + OFF_WO, nullptr, nullptr, o, NROWS, ZZ, ZZ);
    // 7) gate hidden = gelu(o @ Wg1_top + z_pred @ Wg1_bot + bg1) -> qln
    mm_tf32<false,false,false,false,false><<<dim3(ZZ/128, NROWS/128), 256, MM_SMEM>>>(
        o, wr + OFF_WG1, nullptr, nullptr, qln, NROWS, ZZ, ZZ);
    mm_tf32<true,true,true,false,false><<<dim3(ZZ/128, NROWS/128), 256, MM_SMEM>>>(
        zpr, wr + OFF_WG1 + (size_t)ZZ * ZZ, bg1, nullptr, qln, NROWS, ZZ, ZZ);
    // 8) gate scalar + z_mid -> att (fp32) + q (tf32)
    gate_zmid_kernel<<<NROWS, 128>>>(qln, Wg2, bg2, z_pred, o, g_lno, b_lno, att, q);
    // 9) hidden = gelu(z_mid @ W_ff1 + b_ff1) (tf32)
    mm_tf32<false,true,true,false,true><<<dim3((4*ZZ)/128, NROWS/128), 256, MM_SMEM>>>(
        q, wr + OFF_FF1, b_ff1, nullptr, hid, NROWS, ZZ, 4*ZZ);
    // 10) out = hidden @ W_ff2 + b_ff2 + z_mid
    mm_tf32<false,true,false,true,false><<<dim3(ZZ/128, NROWS/128), 256, MM_SMEM>>>(
        hid, wr + OFF_FF2, b_ff2, att, out, NROWS, 4*ZZ, ZZ);
}

// round 6
// speedup vs baseline: 4.9028x; 1.5961x over previous
#include <cuda_runtime.h>
#include <cuda_fp16.h>
#include <math.h>
#include <stdint.h>

// ---------------------------------------------------------------------------
// Problem constants
// ---------------------------------------------------------------------------
#define BB 4
#define TT 16
#define AA 512
#define ZZ 512
#define NFF 6
#define NROWS (BB*TT*AA)      // 32768
#define NCUR  (BB*AA)         // 2048
#define NBT   (BB*TT)         // 64

// ---------------------------------------------------------------------------
// Scratch (static device globals; no allocations allowed)
// ---------------------------------------------------------------------------
// fp32 scratch
__device__ float d_q[NROWS*ZZ];          // q projection (attn input)
__device__ float d_o[NROWS*ZZ];          // out = att @ Wo (fp32, gate residual)
__device__ float d_hg[NROWS*ZZ];         // gate hidden (fp32)
__device__ float d_zmid[NROWS*ZZ];       // z_mid fp32 (FF2 residual)
__device__ float d_kc[NCUR*ZZ];
__device__ float d_vc[NCUR*ZZ];
__device__ float d_e[NBT*ZZ];
// fp16 scratch (GEMM A operands)
__device__ __half h_qln[NROWS*ZZ];       // LN(z_pred)
__device__ __half h_att[NROWS*ZZ];       // attention out
__device__ __half h_o[NROWS*ZZ];         // Wo output (gate GEMM input)
__device__ __half h_zp[NROWS*ZZ];        // z_pred half
__device__ __half h_zc[NCUR*ZZ];         // z_current half
__device__ __half h_zmid[NROWS*ZZ];      // z_mid half (FF1 input)
__device__ __half h_hid[NROWS*4*ZZ];     // FF hidden half (FF2 input)
__device__ __half h_w[3670016];          // transposed half weights [M,K]

// offsets into h_w
#define OFF_WQ   0
#define OFF_WK   262144
#define OFF_WV   524288
#define OFF_WO   786432
#define OFF_WG1  1048576          // [512, 1024]
#define OFF_FF1  1572864          // [2048, 512]
#define OFF_FF2  2621440          // [512, 2048]

// ---------------------------------------------------------------------------
// Helpers
// ---------------------------------------------------------------------------
__device__ __forceinline__ float gelu_exact(float x) {
    return 0.5f * x * (1.0f + erff(x * 0.70710678118654752f));
}
__device__ __forceinline__ uint32_t smem_u32(const void* p) {
    uint32_t a;
    asm("{ .reg .u64 t; cvta.to.shared.u64 t, %1; cvt.u32.u64 %0, t; }"
        : "=r"(a) : "l"(p));
    return a;
}
__device__ __forceinline__ void cp_async16(uint32_t s, const void* g) {
    asm volatile("cp.async.cg.shared.global [%0], [%1], 16;" :: "r"(s), "l"(g));
}
__device__ __forceinline__ void cp_commit() {
    asm volatile("cp.async.commit_group;");
}
__device__ __forceinline__ void cp_wait0() { asm volatile("cp.async.wait_group 0;"); }
__device__ __forceinline__ void cp_wait1() { asm volatile("cp.async.wait_group 1;"); }

// m16n8k16 fp16 MMA, fp32 accumulate
__device__ __forceinline__ void mma16(float c[4], uint32_t a0, uint32_t a1,
                                      uint32_t a2, uint32_t a3,
                                      uint32_t b0, uint32_t b1) {
    asm volatile(
        "mma.sync.aligned.m16n8k16.row.col.f32.f16.f16.f32 "
        "{%0,%1,%2,%3},{%4,%5,%6,%7},{%8,%9},{%0,%1,%2,%3};"
        : "+f"(c[0]), "+f"(c[1]), "+f"(c[2]), "+f"(c[3])
        : "r"(a0), "r"(a1), "r"(a2), "r"(a3), "r"(b0), "r"(b1));
}

__device__ __forceinline__ float blockSum128(float v, float* sb) {
    #pragma unroll
    for (int o = 16; o > 0; o >>= 1) v += __shfl_down_sync(0xffffffffu, v, o);
    int w = threadIdx.x >> 5;
    if ((threadIdx.x & 31) == 0) sb[w] = v;
    __syncthreads();
    if (threadIdx.x < 32) {
        float r = (threadIdx.x < 4) ? sb[threadIdx.x] : 0.0f;
        #pragma unroll
        for (int o = 2; o > 0; o >>= 1) r += __shfl_down_sync(0xffffffffu, r, o);
        if (threadIdx.x == 0) sb[0] = r;
    }
    __syncthreads();
    float out = sb[0];
    __syncthreads();
    return out;
}

// ---------------------------------------------------------------------------
// fp32 -> fp16 copy (n4 = n/4)
// ---------------------------------------------------------------------------
__global__ void halfcopy(const float* __restrict__ x, __half* __restrict__ y, int n4) {
    int i = blockIdx.x * blockDim.x + threadIdx.x;
    if (i < n4) {
        float4 v = ((const float4*)x)[i];
        __half2* yo = (__half2*)y;
        yo[2 * i + 0] = __floats2half2_rn(v.x, v.y);
        yo[2 * i + 1] = __floats2half2_rn(v.z, v.w);
    }
}

// ---------------------------------------------------------------------------
// Weight transpose to half: x[K,M] f32 -> y[M,K] f16.  grid(M/32, K/32), block(32,8)
// ---------------------------------------------------------------------------
__global__ void transpose_half(const float* __restrict__ x, __half* __restrict__ y,
                               int K, int M) {
    __shared__ float t[32][33];
    int m0 = blockIdx.x * 32, k0 = blockIdx.y * 32;
    int tx = threadIdx.x, ty = threadIdx.y;
    #pragma unroll
    for (int i = 0; i < 32; i += 8)
        t[ty + i][tx] = x[(size_t)(k0 + ty + i) * M + m0 + tx];
    __syncthreads();
    #pragma unroll
    for (int i = 0; i < 32; i += 8)
        y[(size_t)(m0 + ty + i) * K + k0 + tx] = __float2half(t[tx][ty + i]);
}

// ---------------------------------------------------------------------------
// LayerNorm (per 512-wide row), 128 threads/row; half output
// ---------------------------------------------------------------------------
__global__ void ln_kernel(const float* __restrict__ x,
                          const float* __restrict__ g,
                          const float* __restrict__ b,
                          __half* __restrict__ y) {
    __shared__ float sb[32];
    int row = blockIdx.x;
    int tid = threadIdx.x;
    const float* xr = x + (size_t)row * ZZ;
    float v[4];
    float s = 0.f;
    #pragma unroll
    for (int k = 0; k < 4; k++) { v[k] = xr[tid + k * 128]; s += v[k]; }
    float mean = blockSum128(s, sb) * (1.0f / ZZ);
    float s2 = 0.f;
    #pragma unroll
    for (int k = 0; k < 4; k++) { float d = v[k] - mean; s2 += d * d; }
    float var = blockSum128(s2, sb) * (1.0f / ZZ);
    float rstd = rsqrtf(var + 1e-5f);
    __half* yr = y + (size_t)row * ZZ;
    #pragma unroll
    for (int k = 0; k < 4; k++) {
        int c = tid + k * 128;
        yr[c] = __float2half((v[k] - mean) * rstd * g[c] + b[c]);
    }
}

// ---------------------------------------------------------------------------
// Edge embedding: fourier(actions) @ W_edge + b_edge -> @ We   (64 rows)
// ---------------------------------------------------------------------------
__global__ void edge_kernel(const float* __restrict__ actions,
                            const float* __restrict__ W_edge,
                            const float* __restrict__ b_edge,
                            const float* __restrict__ We,
                            float* __restrict__ eout) {
    __shared__ float feats[38];
    __shared__ float hid[64];
    int bt = blockIdx.x;
    int tid = threadIdx.x;
    if (tid == 0) {
        float dx = actions[bt * 4 + 0];
        float dy = actions[bt * 4 + 1];
        float th = actions[bt * 4 + 2];
        feats[0] = sinf(th);
        feats[1] = cosf(th);
        #pragma unroll
        for (int k = 0; k < NFF; k++) {
            float f = 3.14159265358979323846f * (float)(1 << k);
            feats[2 + 6 * k + 0] = sinf(f * dx);
            feats[2 + 6 * k + 1] = cosf(f * dx);
            feats[2 + 6 * k + 2] = sinf(f * dy);
            feats[2 + 6 * k + 3] = cosf(f * dy);
            feats[2 + 6 * k + 4] = sinf(f * th);
            feats[2 + 6 * k + 5] = cosf(f * th);
        }
    }
    __syncthreads();
    float h = b_edge[tid];
    #pragma unroll
    for (int j = 0; j < 38; j++) h += feats[j] * W_edge[j * 64 + tid];
    hid[tid] = h;
    __syncthreads();
    #pragma unroll
    for (int c = 0; c < 8; c++) {
        int col = c * 64 + tid;
        float acc = 0.f;
        #pragma unroll
        for (int j = 0; j < 64; j++) acc += hid[j] * We[j * ZZ + col];
        eout[(size_t)bt * ZZ + col] = acc;
    }
}

// ---------------------------------------------------------------------------
// fp16 tensor-core GEMM: C[N,M] = A[N,K] @ Bt[M,K]^T  (A, Bt half; fp32 accum)
// 128x128x64 tiles, 2-stage cp.async, 8 warps of 64x32, mma m16n8k16.
// Epilogue flags: ACC (+=C), BIAS, GELU, RES, WF32 (write C), WF16 (write Ch)
// smem halves: As[2][128][72], Bs[2][128][72] -> 73728 B dynamic
// ---------------------------------------------------------------------------
#define MM_SMEM (4 * 9216 * 2)

template<bool ACC, bool BIAS, bool GELU, bool RES, bool WF32, bool WF16>
__global__ void __launch_bounds__(256, 2)
mm_h(const __half* __restrict__ A, const __half* __restrict__ Bt,
     const float* __restrict__ bias, const float* __restrict__ res,
     float* __restrict__ C, __half* __restrict__ Ch,
     int N, int K, int M, int lda, int ldb) {
    extern __shared__ __half smh[];
    const uint32_t base = smem_u32(smh);

    const int tid = threadIdx.x;
    const int lane = tid & 31;
    const int wid = tid >> 5;
    const int wm = (wid >> 2) * 64;
    const int wn = (wid & 3) * 32;
    const int bRow = blockIdx.y * 128;
    const int bCol = blockIdx.x * 128;
    const int gid = lane >> 2;
    const int tig = lane & 3;

    float acc[4][4][4];
    #pragma unroll
    for (int mi = 0; mi < 4; mi++)
        #pragma unroll
        for (int ni = 0; ni < 4; ni++)
            #pragma unroll
            for (int r = 0; r < 4; r++) acc[mi][ni][r] = 0.f;

    // stage offsets in halves: A(s) = s*9216 ; B(s) = 18432 + s*9216
    auto load = [&](int chunk, int s) {
        int k0 = chunk * 64;
        #pragma unroll
        for (int it = 0; it < 4; it++) {
            int idx = tid + it * 256;
            int r = idx >> 3, cs = idx & 7;
            cp_async16(base + (uint32_t)(s * 9216 + r * 72 + cs * 8) * 2,
                       A + (size_t)(bRow + r) * lda + k0 + cs * 8);
        }
        #pragma unroll
        for (int it = 0; it < 4; it++) {
            int idx = tid + it * 256;
            int r = idx >> 3, cs = idx & 7;
            cp_async16(base + (uint32_t)(18432 + s * 9216 + r * 72 + cs * 8) * 2,
                       Bt + (size_t)(bCol + r) * ldb + k0 + cs * 8);
        }
    };

    const int nk = K >> 6;
    load(0, 0); cp_commit();
    if (nk > 1) { load(1, 1); cp_commit(); }

    for (int j = 0; j < nk; j++) {
        int s = j & 1;
        if (j + 1 < nk) cp_wait1(); else cp_wait0();
        __syncthreads();

        const __half* as = smh + s * 9216;
        const __half* bs = smh + 18432 + s * 9216;
        #pragma unroll
        for (int ks = 0; ks < 4; ks++) {
            int h = ks * 16 + tig * 2;
            uint32_t bfr[4][2];
            #pragma unroll
            for (int ni = 0; ni < 4; ni++) {
                int c = wn + ni * 8 + gid;
                bfr[ni][0] = *(const uint32_t*)(bs + c * 72 + h);
                bfr[ni][1] = *(const uint32_t*)(bs + c * 72 + h + 8);
            }
            #pragma unroll
            for (int mi = 0; mi < 4; mi++) {
                int r = wm + mi * 16 + gid;
                uint32_t a0 = *(const uint32_t*)(as + r * 72 + h);
                uint32_t a1 = *(const uint32_t*)(as + (r + 8) * 72 + h);
                uint32_t a2 = *(const uint32_t*)(as + r * 72 + h + 8);
                uint32_t a3 = *(const uint32_t*)(as + (r + 8) * 72 + h + 8);
                #pragma unroll
                for (int ni = 0; ni < 4; ni++)
                    mma16(acc[mi][ni], a0, a1, a2, a3, bfr[ni][0], bfr[ni][1]);
            }
        }
        __syncthreads();
        if (j + 2 < nk) { load(j + 2, s); cp_commit(); }
    }

    // epilogue
    #pragma unroll
    for (int mi = 0; mi < 4; mi++) {
        #pragma unroll
        for (int ni = 0; ni < 4; ni++) {
            int r0 = bRow + wm + mi * 16 + gid;
            int c0 = bCol + wn + ni * 8 + tig * 2;
            #pragma unroll
            for (int half_i = 0; half_i < 2; half_i++) {
                int r = r0 + half_i * 8;
                size_t idx = (size_t)r * M + c0;
                float e0 = acc[mi][ni][half_i * 2 + 0];
                float e1 = acc[mi][ni][half_i * 2 + 1];
                if (ACC)  { float2 cv = *(const float2*)(C + idx); e0 += cv.x; e1 += cv.y; }
                if (BIAS) { e0 += bias[c0]; e1 += bias[c0 + 1]; }
                if (GELU) { e0 = gelu_exact(e0); e1 = gelu_exact(e1); }
                if (RES)  { float2 rv = *(const float2*)(res + idx); e0 += rv.x; e1 += rv.y; }
                if (WF32) { *(float2*)(C + idx) = make_float2(e0, e1); }
                if (WF16) { *(__half2*)(Ch + idx) = __floats2half2_rn(e0, e1); }
            }
        }
    }
}

// ---------------------------------------------------------------------------
// Per-dim head-mixing attention (half output; feeds Wo GEMM)
// ---------------------------------------------------------------------------
__global__ void attn_kernel(const float* __restrict__ q,
                            const float* __restrict__ kc,
                            const float* __restrict__ vc,
                            const float* __restrict__ e,
                            __half* __restrict__ att) {
    int idx = blockIdx.x * blockDim.x + threadIdx.x;
    int d = idx & 63;
    int row = idx >> 6;          // bta
    int a = row & (AA - 1);
    int bt = row >> 9;
    int b = bt >> 4;
    const float* qr = q + (size_t)row * ZZ;
    const float* kr = kc + (size_t)(b * AA + a) * ZZ;
    const float* vr = vc + (size_t)(b * AA + a) * ZZ;
    const float* er = e + (size_t)bt * ZZ;
    float qv[8], kv[8], vv[8];
    #pragma unroll
    for (int h = 0; h < 8; h++) {
        int o = h * 64 + d;
        qv[h] = qr[o] * 0.125f;
        kv[h] = kr[o] + er[o];
        vv[h] = vr[o];
    }
    __half* outr = att + (size_t)row * ZZ;
    #pragma unroll
    for (int i = 0; i < 8; i++) {
        float l[8], m = -1e30f;
        #pragma unroll
        for (int j = 0; j < 8; j++) { l[j] = qv[i] * kv[j]; m = fmaxf(m, l[j]); }
        float s = 0.f, o = 0.f;
        #pragma unroll
        for (int j = 0; j < 8; j++) {
            float p = expf(l[j] - m);
            s += p;
            o += p * vv[j];
        }
        outr[i * 64 + d] = __float2half(o / s);
    }
}

// ---------------------------------------------------------------------------
// Gate scalar + z_mid LN, 128 threads/row; writes fp32 + half z_mid
// ---------------------------------------------------------------------------
__global__ void gate_zmid_kernel(const float* __restrict__ hgate,
                                 const float* __restrict__ Wg2,
                                 const float* __restrict__ bg2,
                                 const float* __restrict__ zpred,
                                 const float* __restrict__ outb,
                                 const float* __restrict__ g_lno,
                                 const float* __restrict__ b_lno,
                                 float* __restrict__ zmid,
                                 __half* __restrict__ zmidH) {
    __shared__ float sb[32];
    int row = blockIdx.x;
    int tid = threadIdx.x;
    const float* hr = hgate + (size_t)row * ZZ;
    float p = 0.f;
    #pragma unroll
    for (int k = 0; k < 4; k++) {
        int c = tid + k * 128;
        p += hr[c] * Wg2[c];
    }
    float dot = blockSum128(p, sb);
    float g = 1.0f / (1.0f + expf(-(dot + bg2[0])));

    const float* zr = zpred + (size_t)row * ZZ;
    const float* orow = outb + (size_t)row * ZZ;
    float y[4];
    float s = 0.f;
    #pragma unroll
    for (int k = 0; k < 4; k++) {
        int c = tid + k * 128;
        y[k] = zr[c] + g * orow[c];
        s += y[k];
    }
    float mean = blockSum128(s, sb) * (1.0f / ZZ);
    float s2 = 0.f;
    #pragma unroll
    for (int k = 0; k < 4; k++) { float d = y[k] - mean; s2 += d * d; }
    float var = blockSum128(s2, sb) * (1.0f / ZZ);
    float rstd = rsqrtf(var + 1e-5f);
    float* zm = zmid + (size_t)row * ZZ;
    __half* zmh = zmidH + (size_t)row * ZZ;
    #pragma unroll
    for (int k = 0; k < 4; k++) {
        int c = tid + k * 128;
        float v = (y[k] - mean) * rstd * g_lno[c] + b_lno[c];
        zm[c] = v;
        zmh[c] = __float2half(v);
    }
}

// ---------------------------------------------------------------------------
// Launch
// ---------------------------------------------------------------------------
extern "C" void kernel_launch(void* const* d_in, const int* in_sizes, int n_in,
                              void* d_out, int out_size) {
    const float* z_current = (const float*)d_in[0];
    const float* z_pred    = (const float*)d_in[1];
    const float* actions   = (const float*)d_in[2];
    const float* Wq        = (const float*)d_in[3];
    const float* Wk        = (const float*)d_in[4];
    const float* Wv        = (const float*)d_in[5];
    const float* We        = (const float*)d_in[6];
    const float* Wo        = (const float*)d_in[7];
    const float* g_lnq     = (const float*)d_in[8];
    const float* b_lnq     = (const float*)d_in[9];
    const float* g_lno     = (const float*)d_in[10];
    const float* b_lno     = (const float*)d_in[11];
    const float* W_ff1     = (const float*)d_in[12];
    const float* b_ff1     = (const float*)d_in[13];
    const float* W_ff2     = (const float*)d_in[14];
    const float* b_ff2     = (const float*)d_in[15];
    const float* W_edge    = (const float*)d_in[16];
    const float* b_edge    = (const float*)d_in[17];
    const float* Wg1       = (const float*)d_in[18];
    const float* bg1       = (const float*)d_in[19];
    const float* Wg2       = (const float*)d_in[20];
    const float* bg2       = (const float*)d_in[21];
    float* out = (float*)d_out;

    void *pq, *po, *phg, *pzm, *pkc, *pvc, *pe;
    void *pqln, *patt, *pho, *phzp, *phzc, *phzm, *phhid, *phw;
    cudaGetSymbolAddress(&pq,   d_q);
    cudaGetSymbolAddress(&po,   d_o);
    cudaGetSymbolAddress(&phg,  d_hg);
    cudaGetSymbolAddress(&pzm,  d_zmid);
    cudaGetSymbolAddress(&pkc,  d_kc);
    cudaGetSymbolAddress(&pvc,  d_vc);
    cudaGetSymbolAddress(&pe,   d_e);
    cudaGetSymbolAddress(&pqln, h_qln);
    cudaGetSymbolAddress(&patt, h_att);
    cudaGetSymbolAddress(&pho,  h_o);
    cudaGetSymbolAddress(&phzp, h_zp);
    cudaGetSymbolAddress(&phzc, h_zc);
    cudaGetSymbolAddress(&phzm, h_zmid);
    cudaGetSymbolAddress(&phhid,h_hid);
    cudaGetSymbolAddress(&phw,  h_w);
    float* q    = (float*)pq;
    float* o    = (float*)po;
    float* hg   = (float*)phg;
    float* zmid = (float*)pzm;
    float* kc   = (float*)pkc;
    float* vc   = (float*)pvc;
    float* e    = (float*)pe;
    __half* qln = (__half*)pqln;
    __half* att = (__half*)patt;
    __half* oh  = (__half*)pho;
    __half* zp  = (__half*)phzp;
    __half* zc  = (__half*)phzc;
    __half* zmh = (__half*)phzm;
    __half* hid = (__half*)phhid;
    __half* wh  = (__half*)phw;

    cudaFuncSetAttribute(mm_h<false,false,false,false,true,false>,
                         cudaFuncAttributeMaxDynamicSharedMemorySize, MM_SMEM);
    cudaFuncSetAttribute(mm_h<false,false,false,false,true,true>,
                         cudaFuncAttributeMaxDynamicSharedMemorySize, MM_SMEM);
    cudaFuncSetAttribute(mm_h<true,true,true,false,true,false>,
                         cudaFuncAttributeMaxDynamicSharedMemorySize, MM_SMEM);
    cudaFuncSetAttribute(mm_h<false,true,true,false,false,true>,
                         cudaFuncAttributeMaxDynamicSharedMemorySize, MM_SMEM);
    cudaFuncSetAttribute(mm_h<false,true,false,true,true,false>,
                         cudaFuncAttributeMaxDynamicSharedMemorySize, MM_SMEM);

    // 0) prep: transposed half weights + half activations
    dim3 tb(32, 8);
    transpose_half<<<dim3(512/32,  512/32),  tb>>>(Wq,    wh + OFF_WQ,  512,  512);
    transpose_half<<<dim3(512/32,  512/32),  tb>>>(Wk,    wh + OFF_WK,  512,  512);
    transpose_half<<<dim3(512/32,  512/32),  tb>>>(Wv,    wh + OFF_WV,  512,  512);
    transpose_half<<<dim3(512/32,  512/32),  tb>>>(Wo,    wh + OFF_WO,  512,  512);
    transpose_half<<<dim3(512/32,  1024/32), tb>>>(Wg1,   wh + OFF_WG1, 1024, 512);
    transpose_half<<<dim3(2048/32, 512/32),  tb>>>(W_ff1, wh + OFF_FF1, 512,  2048);
    transpose_half<<<dim3(512/32,  2048/32), tb>>>(W_ff2, wh + OFF_FF2, 2048, 512);
    halfcopy<<<((NCUR*ZZ)/4+255)/256,  256>>>(z_current, zc, (NCUR*ZZ)/4);
    halfcopy<<<((NROWS*ZZ)/4+255)/256, 256>>>(z_pred,    zp, (NROWS*ZZ)/4);

    // 1) LN(z_pred) -> qln (half)
    ln_kernel<<<NROWS, 128>>>(z_pred, g_lnq, b_lnq, qln);
    // 2) edge embedding
    edge_kernel<<<NBT, 64>>>(actions, W_edge, b_edge, We, e);
    // 3) q = qln @ Wq -> f32
    mm_h<false,false,false,false,true,false><<<dim3(4, 256), 256, MM_SMEM>>>(
        qln, wh + OFF_WQ, nullptr, nullptr, q, nullptr, NROWS, ZZ, ZZ, ZZ, ZZ);
    // 4) kc, vc -> f32
    mm_h<false,false,false,false,true,false><<<dim3(4, 16), 256, MM_SMEM>>>(
        zc, wh + OFF_WK, nullptr, nullptr, kc, nullptr, NCUR, ZZ, ZZ, ZZ, ZZ);
    mm_h<false,false,false,false,true,false><<<dim3(4, 16), 256, MM_SMEM>>>(
        zc, wh + OFF_WV, nullptr, nullptr, vc, nullptr, NCUR, ZZ, ZZ, ZZ, ZZ);
    // 5) attention -> att (half)
    attn_kernel<<<(NROWS * 64) / 256, 256>>>(q, kc, vc, e, att);
    // 6) o = att @ Wo -> f32 + half
    mm_h<false,false,false,false,true,true><<<dim3(4, 256), 256, MM_SMEM>>>(
        att, wh + OFF_WO, nullptr, nullptr, o, oh, NROWS, ZZ, ZZ, ZZ, ZZ);
    // 7) gate hidden = gelu(o @ Wg1_top + z_pred @ Wg1_bot + bg1) -> hg f32
    mm_h<false,false,false,false,true,false><<<dim3(4, 256), 256, MM_SMEM>>>(
        oh, wh + OFF_WG1, nullptr, nullptr, hg, nullptr, NROWS, ZZ, ZZ, ZZ, 1024);
    mm_h<true,true,true,false,true,false><<<dim3(4, 256), 256, MM_SMEM>>>(
        zp, wh + OFF_WG1 + 512, bg1, nullptr, hg, nullptr, NROWS, ZZ, ZZ, ZZ, 1024);
    // 8) gate scalar + z_mid -> zmid f32 + zmh half
    gate_zmid_kernel<<<NROWS, 128>>>(hg, Wg2, bg2, z_pred, o, g_lno, b_lno, zmid, zmh);
    // 9) hidden = gelu(z_mid @ W_ff1 + b_ff1) -> half only
    mm_h<false,true,true,false,false,true><<<dim3(16, 256), 256, MM_SMEM>>>(
        zmh, wh + OFF_FF1, b_ff1, nullptr, nullptr, hid, NROWS, ZZ, 4*ZZ, ZZ, ZZ);
    // 10) out = hidden @ W_ff2 + b_ff2 + z_mid -> f32
    mm_h<false,true,false,true,true,false><<<dim3(4, 256), 256, MM_SMEM>>>(
        hid, wh + OFF_FF2, b_ff2, zmid, out, nullptr, NROWS, 4*ZZ, ZZ, 4*ZZ, 4*ZZ);
}

// round 7
// speedup vs baseline: 5.5384x; 1.1297x over previous
#include <cuda_runtime.h>
#include <cuda_fp16.h>
#include <math.h>
#include <stdint.h>

// ---------------------------------------------------------------------------
// Problem constants
// ---------------------------------------------------------------------------
#define BB 4
#define TT 16
#define AA 512
#define ZZ 512
#define NFF 6
#define NROWS (BB*TT*AA)      // 32768
#define NCUR  (BB*AA)         // 2048
#define NBT   (BB*TT)         // 64

// ---------------------------------------------------------------------------
// Scratch (static device globals; no allocations allowed)
// ---------------------------------------------------------------------------
// fp32 scratch
__device__ float d_o[NROWS*ZZ];          // out = att @ Wo (fp32, gate residual)
__device__ float d_zmid[NROWS*ZZ];       // z_mid fp32 (FF2 residual)
__device__ float d_kc[NCUR*ZZ];
__device__ float d_vc[NCUR*ZZ];
__device__ float d_e[NBT*ZZ];
// fp16 scratch
__device__ __half h_qln[NROWS*ZZ];       // LN(z_pred) (Q GEMM input)
__device__ __half h_q[NROWS*ZZ];         // q projection (attn input)
__device__ __half h_att[NROWS*ZZ];       // attention out (Wo input)
__device__ __half h_cat[NROWS*2*ZZ];     // [o | z_pred] concat (gate GEMM input)
__device__ __half h_hg[NROWS*ZZ];        // gate hidden (gelu'd, half)
__device__ __half h_zc[NCUR*ZZ];         // z_current half
__device__ __half h_zmid[NROWS*ZZ];      // z_mid half (FF1 input)
__device__ __half h_hid[NROWS*4*ZZ];     // FF hidden half (FF2 input)
__device__ __half h_w[3670016];          // transposed half weights [M,K]

// offsets into h_w
#define OFF_WQ   0
#define OFF_WK   262144
#define OFF_WV   524288
#define OFF_WO   786432
#define OFF_WG1  1048576          // [512, 1024]
#define OFF_FF1  1572864          // [2048, 512]
#define OFF_FF2  2621440          // [512, 2048]

// ---------------------------------------------------------------------------
// Helpers
// ---------------------------------------------------------------------------
__device__ __forceinline__ float gelu_exact(float x) {
    return 0.5f * x * (1.0f + erff(x * 0.70710678118654752f));
}
__device__ __forceinline__ uint32_t smem_u32(const void* p) {
    uint32_t a;
    asm("{ .reg .u64 t; cvta.to.shared.u64 t, %1; cvt.u32.u64 %0, t; }"
        : "=r"(a) : "l"(p));
    return a;
}
__device__ __forceinline__ void cp_async16(uint32_t s, const void* g) {
    asm volatile("cp.async.cg.shared.global [%0], [%1], 16;" :: "r"(s), "l"(g));
}
__device__ __forceinline__ void cp_commit() {
    asm volatile("cp.async.commit_group;");
}
__device__ __forceinline__ void cp_wait0() { asm volatile("cp.async.wait_group 0;"); }
__device__ __forceinline__ void cp_wait1() { asm volatile("cp.async.wait_group 1;"); }

// m16n8k16 fp16 MMA, fp32 accumulate
__device__ __forceinline__ void mma16(float c[4], uint32_t a0, uint32_t a1,
                                      uint32_t a2, uint32_t a3,
                                      uint32_t b0, uint32_t b1) {
    asm volatile(
        "mma.sync.aligned.m16n8k16.row.col.f32.f16.f16.f32 "
        "{%0,%1,%2,%3},{%4,%5,%6,%7},{%8,%9},{%0,%1,%2,%3};"
        : "+f"(c[0]), "+f"(c[1]), "+f"(c[2]), "+f"(c[3])
        : "r"(a0), "r"(a1), "r"(a2), "r"(a3), "r"(b0), "r"(b1));
}

__device__ __forceinline__ void ldsm4(uint32_t& r0, uint32_t& r1,
                                      uint32_t& r2, uint32_t& r3, uint32_t a) {
    asm volatile("ldmatrix.sync.aligned.m8n8.x4.shared.b16 {%0,%1,%2,%3}, [%4];"
        : "=r"(r0), "=r"(r1), "=r"(r2), "=r"(r3) : "r"(a));
}

__device__ __forceinline__ float blockSum128(float v, float* sb) {
    #pragma unroll
    for (int o = 16; o > 0; o >>= 1) v += __shfl_down_sync(0xffffffffu, v, o);
    int w = threadIdx.x >> 5;
    if ((threadIdx.x & 31) == 0) sb[w] = v;
    __syncthreads();
    if (threadIdx.x < 32) {
        float r = (threadIdx.x < 4) ? sb[threadIdx.x] : 0.0f;
        #pragma unroll
        for (int o = 2; o > 0; o >>= 1) r += __shfl_down_sync(0xffffffffu, r, o);
        if (threadIdx.x == 0) sb[0] = r;
    }
    __syncthreads();
    float out = sb[0];
    __syncthreads();
    return out;
}

// ---------------------------------------------------------------------------
// fp32 -> fp16 copy (n4 = n/4)
// ---------------------------------------------------------------------------
__global__ void halfcopy(const float* __restrict__ x, __half* __restrict__ y, int n4) {
    int i = blockIdx.x * blockDim.x + threadIdx.x;
    if (i < n4) {
        float4 v = ((const float4*)x)[i];
        __half2* yo = (__half2*)y;
        yo[2 * i + 0] = __floats2half2_rn(v.x, v.y);
        yo[2 * i + 1] = __floats2half2_rn(v.z, v.w);
    }
}

// ---------------------------------------------------------------------------
// Weight transpose to half: x[K,M] f32 -> y[M,K] f16.  grid(M/32, K/32), block(32,8)
// ---------------------------------------------------------------------------
__global__ void transpose_half(const float* __restrict__ x, __half* __restrict__ y,
                               int K, int M) {
    __shared__ float t[32][33];
    int m0 = blockIdx.x * 32, k0 = blockIdx.y * 32;
    int tx = threadIdx.x, ty = threadIdx.y;
    #pragma unroll
    for (int i = 0; i < 32; i += 8)
        t[ty + i][tx] = x[(size_t)(k0 + ty + i) * M + m0 + tx];
    __syncthreads();
    #pragma unroll
    for (int i = 0; i < 32; i += 8)
        y[(size_t)(m0 + ty + i) * K + k0 + tx] = __float2half(t[tx][ty + i]);
}

// ---------------------------------------------------------------------------
// LayerNorm (per 512-wide row), 128 threads/row; writes half LN output AND
// deposits half(z_pred) into the concat buffer's upper 512 columns.
// ---------------------------------------------------------------------------
__global__ void ln_kernel(const float* __restrict__ x,
                          const float* __restrict__ g,
                          const float* __restrict__ b,
                          __half* __restrict__ y,
                          __half* __restrict__ cat) {
    __shared__ float sb[32];
    int row = blockIdx.x;
    int tid = threadIdx.x;
    const float* xr = x + (size_t)row * ZZ;
    float v[4];
    float s = 0.f;
    #pragma unroll
    for (int k = 0; k < 4; k++) { v[k] = xr[tid + k * 128]; s += v[k]; }
    float mean = blockSum128(s, sb) * (1.0f / ZZ);
    float s2 = 0.f;
    #pragma unroll
    for (int k = 0; k < 4; k++) { float d = v[k] - mean; s2 += d * d; }
    float var = blockSum128(s2, sb) * (1.0f / ZZ);
    float rstd = rsqrtf(var + 1e-5f);
    __half* yr = y + (size_t)row * ZZ;
    __half* cr = cat + (size_t)row * (2 * ZZ) + ZZ;
    #pragma unroll
    for (int k = 0; k < 4; k++) {
        int c = tid + k * 128;
        yr[c] = __float2half((v[k] - mean) * rstd * g[c] + b[c]);
        cr[c] = __float2half(v[k]);
    }
}

// ---------------------------------------------------------------------------
// Edge embedding: fourier(actions) @ W_edge + b_edge -> @ We   (64 rows)
// ---------------------------------------------------------------------------
__global__ void edge_kernel(const float* __restrict__ actions,
                            const float* __restrict__ W_edge,
                            const float* __restrict__ b_edge,
                            const float* __restrict__ We,
                            float* __restrict__ eout) {
    __shared__ float feats[38];
    __shared__ float hid[64];
    int bt = blockIdx.x;
    int tid = threadIdx.x;
    if (tid == 0) {
        float dx = actions[bt * 4 + 0];
        float dy = actions[bt * 4 + 1];
        float th = actions[bt * 4 + 2];
        feats[0] = sinf(th);
        feats[1] = cosf(th);
        #pragma unroll
        for (int k = 0; k < NFF; k++) {
            float f = 3.14159265358979323846f * (float)(1 << k);
            feats[2 + 6 * k + 0] = sinf(f * dx);
            feats[2 + 6 * k + 1] = cosf(f * dx);
            feats[2 + 6 * k + 2] = sinf(f * dy);
            feats[2 + 6 * k + 3] = cosf(f * dy);
            feats[2 + 6 * k + 4] = sinf(f * th);
            feats[2 + 6 * k + 5] = cosf(f * th);
        }
    }
    __syncthreads();
    float h = b_edge[tid];
    #pragma unroll
    for (int j = 0; j < 38; j++) h += feats[j] * W_edge[j * 64 + tid];
    hid[tid] = h;
    __syncthreads();
    #pragma unroll
    for (int c = 0; c < 8; c++) {
        int col = c * 64 + tid;
        float acc = 0.f;
        #pragma unroll
        for (int j = 0; j < 64; j++) acc += hid[j] * We[j * ZZ + col];
        eout[(size_t)bt * ZZ + col] = acc;
    }
}

// ---------------------------------------------------------------------------
// fp16 tensor-core GEMM: C[N,M] = A[N,K] @ Bt[M,K]^T  (A, Bt half; fp32 accum)
// 128x128x64 tiles, 2-stage cp.async, 8 warps of 64x32, mma m16n8k16, ldmatrix.
// Epilogue: BIAS, GELU, RES, WF32 (write C f32, stride M), WF16 (write Ch, ldch)
// smem halves: As[2][128][72], Bs[2][128][72] -> 73728 B dynamic
// ---------------------------------------------------------------------------
#define MM_SMEM (4 * 9216 * 2)

template<bool BIAS, bool GELU, bool RES, bool WF32, bool WF16>
__global__ void __launch_bounds__(256, 2)
mm_h(const __half* __restrict__ A, const __half* __restrict__ Bt,
     const float* __restrict__ bias, const float* __restrict__ res,
     float* __restrict__ C, __half* __restrict__ Ch,
     int K, int M, int lda, int ldb, int ldch) {
    extern __shared__ __half smh[];
    const uint32_t base = smem_u32(smh);

    const int tid = threadIdx.x;
    const int lane = tid & 31;
    const int wid = tid >> 5;
    const int wm = (wid >> 2) * 64;
    const int wn = (wid & 3) * 32;
    const int bRow = blockIdx.y * 128;
    const int bCol = blockIdx.x * 128;
    const int gid = lane >> 2;
    const int tig = lane & 3;

    // ldmatrix per-lane row/col selects
    const int lr = lane & 7;
    const int aRow = wm + lr + ((lane >> 3) & 1) * 8;   // + mi*16
    const int aK   = ((lane >> 4) & 1) * 8;             // + ks*16
    const int bRw  = wn + lr + ((lane >> 4) & 1) * 8;   // + pair*16
    const int bK   = ((lane >> 3) & 1) * 8;             // + ks*16

    float acc[4][4][4];
    #pragma unroll
    for (int mi = 0; mi < 4; mi++)
        #pragma unroll
        for (int ni = 0; ni < 4; ni++)
            #pragma unroll
            for (int r = 0; r < 4; r++) acc[mi][ni][r] = 0.f;

    // stage offsets in halves: A(s) = s*9216 ; B(s) = 18432 + s*9216
    auto load = [&](int chunk, int s) {
        int k0 = chunk * 64;
        #pragma unroll
        for (int it = 0; it < 4; it++) {
            int idx = tid + it * 256;
            int r = idx >> 3, cs = idx & 7;
            cp_async16(base + (uint32_t)(s * 9216 + r * 72 + cs * 8) * 2,
                       A + (size_t)(bRow + r) * lda + k0 + cs * 8);
        }
        #pragma unroll
        for (int it = 0; it < 4; it++) {
            int idx = tid + it * 256;
            int r = idx >> 3, cs = idx & 7;
            cp_async16(base + (uint32_t)(18432 + s * 9216 + r * 72 + cs * 8) * 2,
                       Bt + (size_t)(bCol + r) * ldb + k0 + cs * 8);
        }
    };

    const int nk = K >> 6;
    load(0, 0); cp_commit();
    if (nk > 1) { load(1, 1); cp_commit(); }

    for (int j = 0; j < nk; j++) {
        int s = j & 1;
        if (j + 1 < nk) cp_wait1(); else cp_wait0();
        __syncthreads();

        uint32_t aBase = base + (uint32_t)(s * 9216 + aRow * 72 + aK) * 2;
        uint32_t bBase = base + (uint32_t)(18432 + s * 9216 + bRw * 72 + bK) * 2;
        #pragma unroll
        for (int ks = 0; ks < 4; ks++) {
            uint32_t af[4][4];
            #pragma unroll
            for (int mi = 0; mi < 4; mi++)
                ldsm4(af[mi][0], af[mi][1], af[mi][2], af[mi][3],
                      aBase + (uint32_t)(mi * 16 * 72 + ks * 16) * 2);
            uint32_t bf[4][2];
            ldsm4(bf[0][0], bf[0][1], bf[1][0], bf[1][1],
                  bBase + (uint32_t)(ks * 16) * 2);
            ldsm4(bf[2][0], bf[2][1], bf[3][0], bf[3][1],
                  bBase + (uint32_t)(16 * 72 + ks * 16) * 2);
            #pragma unroll
            for (int mi = 0; mi < 4; mi++)
                #pragma unroll
                for (int ni = 0; ni < 4; ni++)
                    mma16(acc[mi][ni], af[mi][0], af[mi][1], af[mi][2], af[mi][3],
                          bf[ni][0], bf[ni][1]);
        }
        __syncthreads();
        if (j + 2 < nk) { load(j + 2, s); cp_commit(); }
    }

    // epilogue
    #pragma unroll
    for (int mi = 0; mi < 4; mi++) {
        #pragma unroll
        for (int ni = 0; ni < 4; ni++) {
            int r0 = bRow + wm + mi * 16 + gid;
            int c0 = bCol + wn + ni * 8 + tig * 2;
            #pragma unroll
            for (int hi = 0; hi < 2; hi++) {
                int r = r0 + hi * 8;
                float e0 = acc[mi][ni][hi * 2 + 0];
                float e1 = acc[mi][ni][hi * 2 + 1];
                if (BIAS) { e0 += bias[c0]; e1 += bias[c0 + 1]; }
                if (GELU) { e0 = gelu_exact(e0); e1 = gelu_exact(e1); }
                if (RES) {
                    size_t ridx = (size_t)r * M + c0;
                    float2 rv = *(const float2*)(res + ridx);
                    e0 += rv.x; e1 += rv.y;
                }
                if (WF32) {
                    size_t idx = (size_t)r * M + c0;
                    *(float2*)(C + idx) = make_float2(e0, e1);
                }
                if (WF16) {
                    size_t idx = (size_t)r * ldch + c0;
                    *(__half2*)(Ch + idx) = __floats2half2_rn(e0, e1);
                }
            }
        }
    }
}

// ---------------------------------------------------------------------------
// Per-dim head-mixing attention (half q in, half out; feeds Wo GEMM)
// ---------------------------------------------------------------------------
__global__ void attn_kernel(const __half* __restrict__ q,
                            const float* __restrict__ kc,
                            const float* __restrict__ vc,
                            const float* __restrict__ e,
                            __half* __restrict__ att) {
    int idx = blockIdx.x * blockDim.x + threadIdx.x;
    int d = idx & 63;
    int row = idx >> 6;          // bta
    int a = row & (AA - 1);
    int bt = row >> 9;
    int b = bt >> 4;
    const __half* qr = q + (size_t)row * ZZ;
    const float* kr = kc + (size_t)(b * AA + a) * ZZ;
    const float* vr = vc + (size_t)(b * AA + a) * ZZ;
    const float* er = e + (size_t)bt * ZZ;
    float qv[8], kv[8], vv[8];
    #pragma unroll
    for (int h = 0; h < 8; h++) {
        int o = h * 64 + d;
        qv[h] = __half2float(qr[o]) * 0.125f;
        kv[h] = kr[o] + er[o];
        vv[h] = vr[o];
    }
    __half* outr = att + (size_t)row * ZZ;
    #pragma unroll
    for (int i = 0; i < 8; i++) {
        float l[8], m = -1e30f;
        #pragma unroll
        for (int j = 0; j < 8; j++) { l[j] = qv[i] * kv[j]; m = fmaxf(m, l[j]); }
        float s = 0.f, o = 0.f;
        #pragma unroll
        for (int j = 0; j < 8; j++) {
            float p = expf(l[j] - m);
            s += p;
            o += p * vv[j];
        }
        outr[i * 64 + d] = __float2half(o / s);
    }
}

// ---------------------------------------------------------------------------
// Gate scalar + z_mid LN, 128 threads/row; writes fp32 + half z_mid
// ---------------------------------------------------------------------------
__global__ void gate_zmid_kernel(const __half* __restrict__ hgate,
                                 const float* __restrict__ Wg2,
                                 const float* __restrict__ bg2,
                                 const float* __restrict__ zpred,
                                 const float* __restrict__ outb,
                                 const float* __restrict__ g_lno,
                                 const float* __restrict__ b_lno,
                                 float* __restrict__ zmid,
                                 __half* __restrict__ zmidH) {
    __shared__ float sb[32];
    int row = blockIdx.x;
    int tid = threadIdx.x;
    const __half* hr = hgate + (size_t)row * ZZ;
    float p = 0.f;
    #pragma unroll
    for (int k = 0; k < 4; k++) {
        int c = tid + k * 128;
        p += __half2float(hr[c]) * Wg2[c];
    }
    float dot = blockSum128(p, sb);
    float g = 1.0f / (1.0f + expf(-(dot + bg2[0])));

    const float* zr = zpred + (size_t)row * ZZ;
    const float* orow = outb + (size_t)row * ZZ;
    float y[4];
    float s = 0.f;
    #pragma unroll
    for (int k = 0; k < 4; k++) {
        int c = tid + k * 128;
        y[k] = zr[c] + g * orow[c];
        s += y[k];
    }
    float mean = blockSum128(s, sb) * (1.0f / ZZ);
    float s2 = 0.f;
    #pragma unroll
    for (int k = 0; k < 4; k++) { float d = y[k] - mean; s2 += d * d; }
    float var = blockSum128(s2, sb) * (1.0f / ZZ);
    float rstd = rsqrtf(var + 1e-5f);
    float* zm = zmid + (size_t)row * ZZ;
    __half* zmh = zmidH + (size_t)row * ZZ;
    #pragma unroll
    for (int k = 0; k < 4; k++) {
        int c = tid + k * 128;
        float v = (y[k] - mean) * rstd * g_lno[c] + b_lno[c];
        zm[c] = v;
        zmh[c] = __float2half(v);
    }
}

// ---------------------------------------------------------------------------
// Launch
// ---------------------------------------------------------------------------
extern "C" void kernel_launch(void* const* d_in, const int* in_sizes, int n_in,
                              void* d_out, int out_size) {
    const float* z_current = (const float*)d_in[0];
    const float* z_pred    = (const float*)d_in[1];
    const float* actions   = (const float*)d_in[2];
    const float* Wq        = (const float*)d_in[3];
    const float* Wk        = (const float*)d_in[4];
    const float* Wv        = (const float*)d_in[5];
    const float* We        = (const float*)d_in[6];
    const float* Wo        = (const float*)d_in[7];
    const float* g_lnq     = (const float*)d_in[8];
    const float* b_lnq     = (const float*)d_in[9];
    const float* g_lno     = (const float*)d_in[10];
    const float* b_lno     = (const float*)d_in[11];
    const float* W_ff1     = (const float*)d_in[12];
    const float* b_ff1     = (const float*)d_in[13];
    const float* W_ff2     = (const float*)d_in[14];
    const float* b_ff2     = (const float*)d_in[15];
    const float* W_edge    = (const float*)d_in[16];
    const float* b_edge    = (const float*)d_in[17];
    const float* Wg1       = (const float*)d_in[18];
    const float* bg1       = (const float*)d_in[19];
    const float* Wg2       = (const float*)d_in[20];
    const float* bg2       = (const float*)d_in[21];
    float* out = (float*)d_out;

    void *po, *pzm, *pkc, *pvc, *pe;
    void *pqln, *pq, *patt, *pcat, *phg, *phzc, *phzm, *phhid, *phw;
    cudaGetSymbolAddress(&po,   d_o);
    cudaGetSymbolAddress(&pzm,  d_zmid);
    cudaGetSymbolAddress(&pkc,  d_kc);
    cudaGetSymbolAddress(&pvc,  d_vc);
    cudaGetSymbolAddress(&pe,   d_e);
    cudaGetSymbolAddress(&pqln, h_qln);
    cudaGetSymbolAddress(&pq,   h_q);
    cudaGetSymbolAddress(&patt, h_att);
    cudaGetSymbolAddress(&pcat, h_cat);
    cudaGetSymbolAddress(&phg,  h_hg);
    cudaGetSymbolAddress(&phzc, h_zc);
    cudaGetSymbolAddress(&phzm, h_zmid);
    cudaGetSymbolAddress(&phhid,h_hid);
    cudaGetSymbolAddress(&phw,  h_w);
    float* o    = (float*)po;
    float* zmid = (float*)pzm;
    float* kc   = (float*)pkc;
    float* vc   = (float*)pvc;
    float* e    = (float*)pe;
    __half* qln = (__half*)pqln;
    __half* qh  = (__half*)pq;
    __half* att = (__half*)patt;
    __half* cat = (__half*)pcat;
    __half* hg  = (__half*)phg;
    __half* zc  = (__half*)phzc;
    __half* zmh = (__half*)phzm;
    __half* hid = (__half*)phhid;
    __half* wh  = (__half*)phw;

    cudaFuncSetAttribute(mm_h<false,false,false,true,false>,
                         cudaFuncAttributeMaxDynamicSharedMemorySize, MM_SMEM);
    cudaFuncSetAttribute(mm_h<false,false,false,false,true>,
                         cudaFuncAttributeMaxDynamicSharedMemorySize, MM_SMEM);
    cudaFuncSetAttribute(mm_h<false,false,false,true,true>,
                         cudaFuncAttributeMaxDynamicSharedMemorySize, MM_SMEM);
    cudaFuncSetAttribute(mm_h<true,true,false,false,true>,
                         cudaFuncAttributeMaxDynamicSharedMemorySize, MM_SMEM);
    cudaFuncSetAttribute(mm_h<true,false,true,true,false>,
                         cudaFuncAttributeMaxDynamicSharedMemorySize, MM_SMEM);

    // 0) prep: transposed half weights + half z_current
    dim3 tb(32, 8);
    transpose_half<<<dim3(512/32,  512/32),  tb>>>(Wq,    wh + OFF_WQ,  512,  512);
    transpose_half<<<dim3(512/32,  512/32),  tb>>>(Wk,    wh + OFF_WK,  512,  512);
    transpose_half<<<dim3(512/32,  512/32),  tb>>>(Wv,    wh + OFF_WV,  512,  512);
    transpose_half<<<dim3(512/32,  512/32),  tb>>>(Wo,    wh + OFF_WO,  512,  512);
    transpose_half<<<dim3(512/32,  1024/32), tb>>>(Wg1,   wh + OFF_WG1, 1024, 512);
    transpose_half<<<dim3(2048/32, 512/32),  tb>>>(W_ff1, wh + OFF_FF1, 512,  2048);
    transpose_half<<<dim3(512/32,  2048/32), tb>>>(W_ff2, wh + OFF_FF2, 2048, 512);
    halfcopy<<<((NCUR*ZZ)/4+255)/256, 256>>>(z_current, zc, (NCUR*ZZ)/4);

    // 1) LN(z_pred) -> qln (half) + cat[:,512:1024] = half(z_pred)
    ln_kernel<<<NROWS, 128>>>(z_pred, g_lnq, b_lnq, qln, cat);
    // 2) edge embedding
    edge_kernel<<<NBT, 64>>>(actions, W_edge, b_edge, We, e);
    // 3) q = qln @ Wq -> half
    mm_h<false,false,false,false,true><<<dim3(4, 256), 256, MM_SMEM>>>(
        qln, wh + OFF_WQ, nullptr, nullptr, nullptr, qh, ZZ, ZZ, ZZ, ZZ, ZZ);
    // 4) kc, vc -> f32
    mm_h<false,false,false,true,false><<<dim3(4, 16), 256, MM_SMEM>>>(
        zc, wh + OFF_WK, nullptr, nullptr, kc, nullptr, ZZ, ZZ, ZZ, ZZ, ZZ);
    mm_h<false,false,false,true,false><<<dim3(4, 16), 256, MM_SMEM>>>(
        zc, wh + OFF_WV, nullptr, nullptr, vc, nullptr, ZZ, ZZ, ZZ, ZZ, ZZ);
    // 5) attention -> att (half)
    attn_kernel<<<(NROWS * 64) / 256, 256>>>(qh, kc, vc, e, att);
    // 6) o = att @ Wo -> f32 (residual) + half into cat[:,0:512]
    mm_h<false,false,false,true,true><<<dim3(4, 256), 256, MM_SMEM>>>(
        att, wh + OFF_WO, nullptr, nullptr, o, cat, ZZ, ZZ, ZZ, ZZ, 2*ZZ);
    // 7) gate hidden = gelu(cat @ Wg1 + bg1) -> hg (half)  [single K=1024 GEMM]
    mm_h<true,true,false,false,true><<<dim3(4, 256), 256, MM_SMEM>>>(
        cat, wh + OFF_WG1, bg1, nullptr, nullptr, hg, 2*ZZ, ZZ, 2*ZZ, 2*ZZ, ZZ);
    // 8) gate scalar + z_mid -> zmid f32 + zmh half
    gate_zmid_kernel<<<NROWS, 128>>>(hg, Wg2, bg2, z_pred, o, g_lno, b_lno, zmid, zmh);
    // 9) hidden = gelu(z_mid @ W_ff1 + b_ff1) -> half
    mm_h<true,true,false,false,true><<<dim3(16, 256), 256, MM_SMEM>>>(
        zmh, wh + OFF_FF1, b_ff1, nullptr, nullptr, hid, ZZ, 4*ZZ, ZZ, ZZ, 4*ZZ);
    // 10) out = hidden @ W_ff2 + b_ff2 + z_mid -> f32
    mm_h<true,false,true,true,false><<<dim3(4, 256), 256, MM_SMEM>>>(
        hid, wh + OFF_FF2, b_ff2, zmid, out, nullptr, 4*ZZ, ZZ, 4*ZZ, 4*ZZ, ZZ);
}

// round 11
// speedup vs baseline: 5.6616x; 1.0222x over previous
#include <cuda_runtime.h>
#include <cuda_fp16.h>
#include <math.h>
#include <stdint.h>

// ---------------------------------------------------------------------------
// Problem constants
// ---------------------------------------------------------------------------
#define BB 4
#define TT 16
#define AA 512
#define ZZ 512
#define NFF 6
#define NROWS (BB*TT*AA)      // 32768
#define NCUR  (BB*AA)         // 2048
#define NBT   (BB*TT)         // 64

// ---------------------------------------------------------------------------
// Scratch (static device globals; no allocations allowed)
// ---------------------------------------------------------------------------
// fp32 scratch
__device__ float d_o[NROWS*ZZ];          // out = att @ Wo (fp32, gate residual)
__device__ float d_zmid[NROWS*ZZ];       // z_mid fp32 (FF2 residual)
__device__ float d_kv[NCUR*2*ZZ];        // [kc | vc] combined (stride 1024)
__device__ float d_e[NBT*ZZ];
// fp16 scratch
__device__ __half h_qln[NROWS*ZZ];       // LN(z_pred) (Q GEMM input)
__device__ __half h_q[NROWS*ZZ];         // q projection, pre-scaled (attn input)
__device__ __half h_att[NROWS*ZZ];       // attention out (Wo input)
__device__ __half h_cat[NROWS*2*ZZ];     // [o | z_pred] concat (gate GEMM input)
__device__ __half h_hg[NROWS*ZZ];        // gate hidden (gelu'd, half)
__device__ __half h_zc[NCUR*ZZ];         // z_current half
__device__ __half h_zmid[NROWS*ZZ];      // z_mid half (FF1 input)
__device__ __half h_hid[NROWS*4*ZZ];     // FF hidden half (FF2 input)
__device__ __half h_w[3670016];          // transposed half weights [M,K]

// offsets into h_w
#define OFF_WQ   0
#define OFF_WK   262144
#define OFF_WV   524288           // contiguous after WK -> combined [1024,512]
#define OFF_WO   786432
#define OFF_WG1  1048576          // [512, 1024]
#define OFF_FF1  1572864          // [2048, 512]
#define OFF_FF2  2621440          // [512, 2048]

// ---------------------------------------------------------------------------
// Helpers
// ---------------------------------------------------------------------------
__device__ __forceinline__ float gelu_exact(float x) {
    return 0.5f * x * (1.0f + erff(x * 0.70710678118654752f));
}
__device__ __forceinline__ uint32_t smem_u32(const void* p) {
    uint32_t a;
    asm("{ .reg .u64 t; cvta.to.shared.u64 t, %1; cvt.u32.u64 %0, t; }"
        : "=r"(a) : "l"(p));
    return a;
}
__device__ __forceinline__ void cp_async16(uint32_t s, const void* g) {
    asm volatile("cp.async.cg.shared.global [%0], [%1], 16;" :: "r"(s), "l"(g));
}
__device__ __forceinline__ void cp_commit() {
    asm volatile("cp.async.commit_group;");
}
__device__ __forceinline__ void cp_wait0() { asm volatile("cp.async.wait_group 0;"); }
__device__ __forceinline__ void cp_wait1() { asm volatile("cp.async.wait_group 1;"); }

// m16n8k16 fp16 MMA, fp32 accumulate
__device__ __forceinline__ void mma16(float c[4], uint32_t a0, uint32_t a1,
                                      uint32_t a2, uint32_t a3,
                                      uint32_t b0, uint32_t b1) {
    asm volatile(
        "mma.sync.aligned.m16n8k16.row.col.f32.f16.f16.f32 "
        "{%0,%1,%2,%3},{%4,%5,%6,%7},{%8,%9},{%0,%1,%2,%3};"
        : "+f"(c[0]), "+f"(c[1]), "+f"(c[2]), "+f"(c[3])
        : "r"(a0), "r"(a1), "r"(a2), "r"(a3), "r"(b0), "r"(b1));
}

__device__ __forceinline__ void ldsm4(uint32_t& r0, uint32_t& r1,
                                      uint32_t& r2, uint32_t& r3, uint32_t a) {
    asm volatile("ldmatrix.sync.aligned.m8n8.x4.shared.b16 {%0,%1,%2,%3}, [%4];"
        : "=r"(r0), "=r"(r1), "=r"(r2), "=r"(r3) : "r"(a));
}

__device__ __forceinline__ float blockSum128(float v, float* sb) {
    #pragma unroll
    for (int o = 16; o > 0; o >>= 1) v += __shfl_down_sync(0xffffffffu, v, o);
    int w = threadIdx.x >> 5;
    if ((threadIdx.x & 31) == 0) sb[w] = v;
    __syncthreads();
    if (threadIdx.x < 32) {
        float r = (threadIdx.x < 4) ? sb[threadIdx.x] : 0.0f;
        #pragma unroll
        for (int o = 2; o > 0; o >>= 1) r += __shfl_down_sync(0xffffffffu, r, o);
        if (threadIdx.x == 0) sb[0] = r;
    }
    __syncthreads();
    float out = sb[0];
    __syncthreads();
    return out;
}

// ---------------------------------------------------------------------------
// Fused prep: ALL weight transposes + z_current halfcopy in ONE launch.
// Transpose x[K,M] f32 -> y[M,K] f16 in 32x32 tiles, 256 flat threads.
// Block ranges:
//   [0,256)      Wq  (scale 0.125)
//   [256,512)    Wk
//   [512,768)    Wv
//   [768,1024)   Wo
//   [1024,1536)  Wg1  (K=1024, M=512)
//   [1536,2560)  FF1  (K=512,  M=2048)
//   [2560,3584)  FF2  (K=2048, M=512)
//   [3584,4608)  halfcopy z_current (1024 blocks x 1024 floats)
// ---------------------------------------------------------------------------
__device__ __forceinline__ void tr_tile(const float* __restrict__ x,
                                        __half* __restrict__ y,
                                        int K, int M, int tile, float scale) {
    __shared__ float t[32][33];
    int tilesX = M >> 5;
    int m0 = (tile % tilesX) * 32;
    int k0 = (tile / tilesX) * 32;
    int tx = threadIdx.x & 31, ty = threadIdx.x >> 5;
    #pragma unroll
    for (int i = 0; i < 32; i += 8)
        t[ty + i][tx] = x[(size_t)(k0 + ty + i) * M + m0 + tx];
    __syncthreads();
    #pragma unroll
    for (int i = 0; i < 32; i += 8)
        y[(size_t)(m0 + ty + i) * K + k0 + tx] = __float2half(t[tx][ty + i] * scale);
}

__global__ void prep_kernel(const float* __restrict__ Wq,
                            const float* __restrict__ Wk,
                            const float* __restrict__ Wv,
                            const float* __restrict__ Wo,
                            const float* __restrict__ Wg1,
                            const float* __restrict__ Wff1,
                            const float* __restrict__ Wff2,
                            const float* __restrict__ zcur,
                            __half* __restrict__ wh,
                            __half* __restrict__ zc) {
    int b = blockIdx.x;
    if (b < 256)        tr_tile(Wq,   wh + OFF_WQ,  512,  512,  b,        0.125f);
    else if (b < 512)   tr_tile(Wk,   wh + OFF_WK,  512,  512,  b - 256,  1.0f);
    else if (b < 768)   tr_tile(Wv,   wh + OFF_WV,  512,  512,  b - 512,  1.0f);
    else if (b < 1024)  tr_tile(Wo,   wh + OFF_WO,  512,  512,  b - 768,  1.0f);
    else if (b < 1536)  tr_tile(Wg1,  wh + OFF_WG1, 1024, 512,  b - 1024, 1.0f);
    else if (b < 2560)  tr_tile(Wff1, wh + OFF_FF1, 512,  2048, b - 1536, 1.0f);
    else if (b < 3584)  tr_tile(Wff2, wh + OFF_FF2, 2048, 512,  b - 2560, 1.0f);
    else {
        int i = (b - 3584) * 256 + threadIdx.x;   // i < 262144 = (NCUR*ZZ)/4
        float4 v = ((const float4*)zcur)[i];
        __half2* yo = (__half2*)zc;
        yo[2 * i + 0] = __floats2half2_rn(v.x, v.y);
        yo[2 * i + 1] = __floats2half2_rn(v.z, v.w);
    }
}

// ---------------------------------------------------------------------------
// LayerNorm (per 512-wide row), 128 threads/row; writes half LN output AND
// deposits half(z_pred) into the concat buffer's upper 512 columns.
// ---------------------------------------------------------------------------
__global__ void ln_kernel(const float* __restrict__ x,
                          const float* __restrict__ g,
                          const float* __restrict__ b,
                          __half* __restrict__ y,
                          __half* __restrict__ cat) {
    __shared__ float sb[32];
    int row = blockIdx.x;
    int tid = threadIdx.x;
    const float* xr = x + (size_t)row * ZZ;
    float v[4];
    float s = 0.f;
    #pragma unroll
    for (int k = 0; k < 4; k++) { v[k] = xr[tid + k * 128]; s += v[k]; }
    float mean = blockSum128(s, sb) * (1.0f / ZZ);
    float s2 = 0.f;
    #pragma unroll
    for (int k = 0; k < 4; k++) { float d = v[k] - mean; s2 += d * d; }
    float var = blockSum128(s2, sb) * (1.0f / ZZ);
    float rstd = rsqrtf(var + 1e-5f);
    __half* yr = y + (size_t)row * ZZ;
    __half* cr = cat + (size_t)row * (2 * ZZ) + ZZ;
    #pragma unroll
    for (int k = 0; k < 4; k++) {
        int c = tid + k * 128;
        yr[c] = __float2half((v[k] - mean) * rstd * g[c] + b[c]);
        cr[c] = __float2half(v[k]);
    }
}

// ---------------------------------------------------------------------------
// Edge embedding: fourier(actions) @ W_edge + b_edge -> @ We   (64 rows)
// ---------------------------------------------------------------------------
__global__ void edge_kernel(const float* __restrict__ actions,
                            const float* __restrict__ W_edge,
                            const float* __restrict__ b_edge,
                            const float* __restrict__ We,
                            float* __restrict__ eout) {
    __shared__ float feats[38];
    __shared__ float hid[64];
    int bt = blockIdx.x;
    int tid = threadIdx.x;
    if (tid == 0) {
        float dx = actions[bt * 4 + 0];
        float dy = actions[bt * 4 + 1];
        float th = actions[bt * 4 + 2];
        feats[0] = sinf(th);
        feats[1] = cosf(th);
        #pragma unroll
        for (int k = 0; k < NFF; k++) {
            float f = 3.14159265358979323846f * (float)(1 << k);
            feats[2 + 6 * k + 0] = sinf(f * dx);
            feats[2 + 6 * k + 1] = cosf(f * dx);
            feats[2 + 6 * k + 2] = sinf(f * dy);
            feats[2 + 6 * k + 3] = cosf(f * dy);
            feats[2 + 6 * k + 4] = sinf(f * th);
            feats[2 + 6 * k + 5] = cosf(f * th);
        }
    }
    __syncthreads();
    float h = b_edge[tid];
    #pragma unroll
    for (int j = 0; j < 38; j++) h += feats[j] * W_edge[j * 64 + tid];
    hid[tid] = h;
    __syncthreads();
    #pragma unroll
    for (int c = 0; c < 8; c++) {
        int col = c * 64 + tid;
        float acc = 0.f;
        #pragma unroll
        for (int j = 0; j < 64; j++) acc += hid[j] * We[j * ZZ + col];
        eout[(size_t)bt * ZZ + col] = acc;
    }
}

// ---------------------------------------------------------------------------
// fp16 tensor-core GEMM: C[N,M] = A[N,K] @ Bt[M,K]^T  (A, Bt half; fp32 accum)
// 128x128x64 tiles, 2-stage cp.async, 8 warps of 64x32, mma m16n8k16, ldmatrix.
// Epilogue: BIAS, GELU, RES, WF32 (write C f32, stride M), WF16 (write Ch, ldch)
// smem halves: As[2][128][72], Bs[2][128][72] -> 73728 B dynamic
// ---------------------------------------------------------------------------
#define MM_SMEM (4 * 9216 * 2)

template<bool BIAS, bool GELU, bool RES, bool WF32, bool WF16>
__global__ void __launch_bounds__(256, 2)
mm_h(const __half* __restrict__ A, const __half* __restrict__ Bt,
     const float* __restrict__ bias, const float* __restrict__ res,
     float* __restrict__ C, __half* __restrict__ Ch,
     int K, int M, int lda, int ldb, int ldch) {
    extern __shared__ __half smh[];
    const uint32_t base = smem_u32(smh);

    const int tid = threadIdx.x;
    const int lane = tid & 31;
    const int wid = tid >> 5;
    const int wm = (wid >> 2) * 64;
    const int wn = (wid & 3) * 32;
    const int bRow = blockIdx.y * 128;
    const int bCol = blockIdx.x * 128;
    const int gid = lane >> 2;
    const int tig = lane & 3;

    // ldmatrix per-lane row/col selects
    const int lr = lane & 7;
    const int aRow = wm + lr + ((lane >> 3) & 1) * 8;   // + mi*16
    const int aK   = ((lane >> 4) & 1) * 8;             // + ks*16
    const int bRw  = wn + lr + ((lane >> 4) & 1) * 8;   // + pair*16
    const int bK   = ((lane >> 3) & 1) * 8;             // + ks*16

    float acc[4][4][4];
    #pragma unroll
    for (int mi = 0; mi < 4; mi++)
        #pragma unroll
        for (int ni = 0; ni < 4; ni++)
            #pragma unroll
            for (int r = 0; r < 4; r++) acc[mi][ni][r] = 0.f;

    // stage offsets in halves: A(s) = s*9216 ; B(s) = 18432 + s*9216
    auto load = [&](int chunk, int s) {
        int k0 = chunk * 64;
        #pragma unroll
        for (int it = 0; it < 4; it++) {
            int idx = tid + it * 256;
            int r = idx >> 3, cs = idx & 7;
            cp_async16(base + (uint32_t)(s * 9216 + r * 72 + cs * 8) * 2,
                       A + (size_t)(bRow + r) * lda + k0 + cs * 8);
        }
        #pragma unroll
        for (int it = 0; it < 4; it++) {
            int idx = tid + it * 256;
            int r = idx >> 3, cs = idx & 7;
            cp_async16(base + (uint32_t)(18432 + s * 9216 + r * 72 + cs * 8) * 2,
                       Bt + (size_t)(bCol + r) * ldb + k0 + cs * 8);
        }
    };

    const int nk = K >> 6;
    load(0, 0); cp_commit();
    if (nk > 1) { load(1, 1); cp_commit(); }

    for (int j = 0; j < nk; j++) {
        int s = j & 1;
        if (j + 1 < nk) cp_wait1(); else cp_wait0();
        __syncthreads();

        uint32_t aBase = base + (uint32_t)(s * 9216 + aRow * 72 + aK) * 2;
        uint32_t bBase = base + (uint32_t)(18432 + s * 9216 + bRw * 72 + bK) * 2;
        #pragma unroll
        for (int ks = 0; ks < 4; ks++) {
            uint32_t af[4][4];
            #pragma unroll
            for (int mi = 0; mi < 4; mi++)
                ldsm4(af[mi][0], af[mi][1], af[mi][2], af[mi][3],
                      aBase + (uint32_t)(mi * 16 * 72 + ks * 16) * 2);
            uint32_t bf[4][2];
            ldsm4(bf[0][0], bf[0][1], bf[1][0], bf[1][1],
                  bBase + (uint32_t)(ks * 16) * 2);
            ldsm4(bf[2][0], bf[2][1], bf[3][0], bf[3][1],
                  bBase + (uint32_t)(16 * 72 + ks * 16) * 2);
            #pragma unroll
            for (int mi = 0; mi < 4; mi++)
                #pragma unroll
                for (int ni = 0; ni < 4; ni++)
                    mma16(acc[mi][ni], af[mi][0], af[mi][1], af[mi][2], af[mi][3],
                          bf[ni][0], bf[ni][1]);
        }
        __syncthreads();
        if (j + 2 < nk) { load(j + 2, s); cp_commit(); }
    }

    // epilogue
    #pragma unroll
    for (int mi = 0; mi < 4; mi++) {
        #pragma unroll
        for (int ni = 0; ni < 4; ni++) {
            int r0 = bRow + wm + mi * 16 + gid;
            int c0 = bCol + wn + ni * 8 + tig * 2;
            #pragma unroll
            for (int hi = 0; hi < 2; hi++) {
                int r = r0 + hi * 8;
                float e0 = acc[mi][ni][hi * 2 + 0];
                float e1 = acc[mi][ni][hi * 2 + 1];
                if (BIAS) { e0 += bias[c0]; e1 += bias[c0 + 1]; }
                if (GELU) { e0 = gelu_exact(e0); e1 = gelu_exact(e1); }
                if (RES) {
                    size_t ridx = (size_t)r * M + c0;
                    float2 rv = *(const float2*)(res + ridx);
                    e0 += rv.x; e1 += rv.y;
                }
                if (WF32) {
                    size_t idx = (size_t)r * M + c0;
                    *(float2*)(C + idx) = make_float2(e0, e1);
                }
                if (WF16) {
                    size_t idx = (size_t)r * ldch + c0;
                    *(__half2*)(Ch + idx) = __floats2half2_rn(e0, e1);
                }
            }
        }
    }
}

// ---------------------------------------------------------------------------
// Per-dim head-mixing attention (half q in, half out; q pre-scaled by 0.125)
// K/V from combined [NCUR, 1024] buffer: cols [0,512)=kc, [512,1024)=vc
// ---------------------------------------------------------------------------
__global__ void attn_kernel(const __half* __restrict__ q,
                            const float* __restrict__ kv,
                            const float* __restrict__ e,
                            __half* __restrict__ att) {
    int idx = blockIdx.x * blockDim.x + threadIdx.x;
    int d = idx & 63;
    int row = idx >> 6;          // bta
    int a = row & (AA - 1);
    int bt = row >> 9;
    int b = bt >> 4;
    const __half* qr = q + (size_t)row * ZZ;
    const float* kr = kv + (size_t)(b * AA + a) * (2 * ZZ);
    const float* er = e + (size_t)bt * ZZ;
    float qv[8], kvv[8], vv[8];
    #pragma unroll
    for (int h = 0; h < 8; h++) {
        int o = h * 64 + d;
        qv[h] = __half2float(qr[o]);
        kvv[h] = kr[o] + er[o];
        vv[h] = kr[ZZ + o];
    }
    __half* outr = att + (size_t)row * ZZ;
    #pragma unroll
    for (int i = 0; i < 8; i++) {
        float l[8], m = -1e30f;
        #pragma unroll
        for (int j = 0; j < 8; j++) { l[j] = qv[i] * kvv[j]; m = fmaxf(m, l[j]); }
        float s = 0.f, o = 0.f;
        #pragma unroll
        for (int j = 0; j < 8; j++) {
            float p = expf(l[j] - m);
            s += p;
            o += p * vv[j];
        }
        outr[i * 64 + d] = __float2half(o / s);
    }
}

// ---------------------------------------------------------------------------
// Gate scalar + z_mid LN, 128 threads/row; writes fp32 + half z_mid
// ---------------------------------------------------------------------------
__global__ void gate_zmid_kernel(const __half* __restrict__ hgate,
                                 const float* __restrict__ Wg2,
                                 const float* __restrict__ bg2,
                                 const float* __restrict__ zpred,
                                 const float* __restrict__ outb,
                                 const float* __restrict__ g_lno,
                                 const float* __restrict__ b_lno,
                                 float* __restrict__ zmid,
                                 __half* __restrict__ zmidH) {
    __shared__ float sb[32];
    int row = blockIdx.x;
    int tid = threadIdx.x;
    const __half* hr = hgate + (size_t)row * ZZ;
    float p = 0.f;
    #pragma unroll
    for (int k = 0; k < 4; k++) {
        int c = tid + k * 128;
        p += __half2float(hr[c]) * Wg2[c];
    }
    float dot = blockSum128(p, sb);
    float g = 1.0f / (1.0f + expf(-(dot + bg2[0])));

    const float* zr = zpred + (size_t)row * ZZ;
    const float* orow = outb + (size_t)row * ZZ;
    float y[4];
    float s = 0.f;
    #pragma unroll
    for (int k = 0; k < 4; k++) {
        int c = tid + k * 128;
        y[k] = zr[c] + g * orow[c];
        s += y[k];
    }
    float mean = blockSum128(s, sb) * (1.0f / ZZ);
    float s2 = 0.f;
    #pragma unroll
    for (int k = 0; k < 4; k++) { float d = y[k] - mean; s2 += d * d; }
    float var = blockSum128(s2, sb) * (1.0f / ZZ);
    float rstd = rsqrtf(var + 1e-5f);
    float* zm = zmid + (size_t)row * ZZ;
    __half* zmh = zmidH + (size_t)row * ZZ;
    #pragma unroll
    for (int k = 0; k < 4; k++) {
        int c = tid + k * 128;
        float v = (y[k] - mean) * rstd * g_lno[c] + b_lno[c];
        zm[c] = v;
        zmh[c] = __float2half(v);
    }
}

// ---------------------------------------------------------------------------
// Launch (single stream; fused prep + merged K/V GEMM shrink the serial chain)
// ---------------------------------------------------------------------------
extern "C" void kernel_launch(void* const* d_in, const int* in_sizes, int n_in,
                              void* d_out, int out_size) {
    const float* z_current = (const float*)d_in[0];
    const float* z_pred    = (const float*)d_in[1];
    const float* actions   = (const float*)d_in[2];
    const float* Wq        = (const float*)d_in[3];
    const float* Wk        = (const float*)d_in[4];
    const float* Wv        = (const float*)d_in[5];
    const float* We        = (const float*)d_in[6];
    const float* Wo        = (const float*)d_in[7];
    const float* g_lnq     = (const float*)d_in[8];
    const float* b_lnq     = (const float*)d_in[9];
    const float* g_lno     = (const float*)d_in[10];
    const float* b_lno     = (const float*)d_in[11];
    const float* W_ff1     = (const float*)d_in[12];
    const float* b_ff1     = (const float*)d_in[13];
    const float* W_ff2     = (const float*)d_in[14];
    const float* b_ff2     = (const float*)d_in[15];
    const float* W_edge    = (const float*)d_in[16];
    const float* b_edge    = (const float*)d_in[17];
    const float* Wg1       = (const float*)d_in[18];
    const float* bg1       = (const float*)d_in[19];
    const float* Wg2       = (const float*)d_in[20];
    const float* bg2       = (const float*)d_in[21];
    float* out = (float*)d_out;

    void *po, *pzm, *pkv, *pe;
    void *pqln, *pq, *patt, *pcat, *phg, *phzc, *phzm, *phhid, *phw;
    cudaGetSymbolAddress(&po,   d_o);
    cudaGetSymbolAddress(&pzm,  d_zmid);
    cudaGetSymbolAddress(&pkv,  d_kv);
    cudaGetSymbolAddress(&pe,   d_e);
    cudaGetSymbolAddress(&pqln, h_qln);
    cudaGetSymbolAddress(&pq,   h_q);
    cudaGetSymbolAddress(&patt, h_att);
    cudaGetSymbolAddress(&pcat, h_cat);
    cudaGetSymbolAddress(&phg,  h_hg);
    cudaGetSymbolAddress(&phzc, h_zc);
    cudaGetSymbolAddress(&phzm, h_zmid);
    cudaGetSymbolAddress(&phhid,h_hid);
    cudaGetSymbolAddress(&phw,  h_w);
    float* o    = (float*)po;
    float* zmid = (float*)pzm;
    float* kv   = (float*)pkv;
    float* e    = (float*)pe;
    __half* qln = (__half*)pqln;
    __half* qh  = (__half*)pq;
    __half* att = (__half*)patt;
    __half* cat = (__half*)pcat;
    __half* hg  = (__half*)phg;
    __half* zc  = (__half*)phzc;
    __half* zmh = (__half*)phzm;
    __half* hid = (__half*)phhid;
    __half* wh  = (__half*)phw;

    cudaFuncSetAttribute(mm_h<false,false,false,true,false>,
                         cudaFuncAttributeMaxDynamicSharedMemorySize, MM_SMEM);
    cudaFuncSetAttribute(mm_h<false,false,false,false,true>,
                         cudaFuncAttributeMaxDynamicSharedMemorySize, MM_SMEM);
    cudaFuncSetAttribute(mm_h<false,false,false,true,true>,
                         cudaFuncAttributeMaxDynamicSharedMemorySize, MM_SMEM);
    cudaFuncSetAttribute(mm_h<true,true,false,false,true>,
                         cudaFuncAttributeMaxDynamicSharedMemorySize, MM_SMEM);
    cudaFuncSetAttribute(mm_h<true,false,true,true,false>,
                         cudaFuncAttributeMaxDynamicSharedMemorySize, MM_SMEM);

    // 0) fused prep: all weight transposes (+Wq scale) + z_current halfcopy
    prep_kernel<<<4608, 256>>>(Wq, Wk, Wv, Wo, Wg1, W_ff1, W_ff2,
                               z_current, wh, zc);
    // 1) LN(z_pred) -> qln (half) + cat[:,512:1024] = half(z_pred)
    ln_kernel<<<NROWS, 128>>>(z_pred, g_lnq, b_lnq, qln, cat);
    // 2) edge embedding
    edge_kernel<<<NBT, 64>>>(actions, W_edge, b_edge, We, e);
    // 3) q = qln @ (Wq/8) -> half
    mm_h<false,false,false,false,true><<<dim3(4, 256), 256, MM_SMEM>>>(
        qln, wh + OFF_WQ, nullptr, nullptr, nullptr, qh, ZZ, ZZ, ZZ, ZZ, ZZ);
    // 4) [kc|vc] = zc @ [Wk|Wv] -> f32 combined (single M=1024 GEMM)
    mm_h<false,false,false,true,false><<<dim3(8, 16), 256, MM_SMEM>>>(
        zc, wh + OFF_WK, nullptr, nullptr, kv, nullptr, ZZ, 2*ZZ, ZZ, ZZ, 2*ZZ);
    // 5) attention -> att (half)
    attn_kernel<<<(NROWS * 64) / 256, 256>>>(qh, kv, e, att);
    // 6) o = att @ Wo -> f32 (residual) + half into cat[:,0:512]
    mm_h<false,false,false,true,true><<<dim3(4, 256), 256, MM_SMEM>>>(
        att, wh + OFF_WO, nullptr, nullptr, o, cat, ZZ, ZZ, ZZ, ZZ, 2*ZZ);
    // 7) gate hidden = gelu(cat @ Wg1 + bg1) -> hg (half)  [single K=1024 GEMM]
    mm_h<true,true,false,false,true><<<dim3(4, 256), 256, MM_SMEM>>>(
        cat, wh + OFF_WG1, bg1, nullptr, nullptr, hg, 2*ZZ, ZZ, 2*ZZ, 2*ZZ, ZZ);
    // 8) gate scalar + z_mid -> zmid f32 + zmh half
    gate_zmid_kernel<<<NROWS, 128>>>(hg, Wg2, bg2, z_pred, o, g_lno, b_lno, zmid, zmh);
    // 9) hidden = gelu(z_mid @ W_ff1 + b_ff1) -> half
    mm_h<true,true,false,false,true><<<dim3(16, 256), 256, MM_SMEM>>>(
        zmh, wh + OFF_FF1, b_ff1, nullptr, nullptr, hid, ZZ, 4*ZZ, ZZ, ZZ, 4*ZZ);
    // 10) out = hidden @ W_ff2 + b_ff2 + z_mid -> f32
    mm_h<true,false,true,true,false><<<dim3(4, 256), 256, MM_SMEM>>>(
        hid, wh + OFF_FF2, b_ff2, zmid, out, nullptr, 4*ZZ, ZZ, 4*ZZ, 4*ZZ, ZZ);
}